// round 13
// baseline (speedup 1.0000x reference)
#include <cuda_runtime.h>
#include <math.h>

#define NB 128
#define DD 192
#define DEPTHL 12
#define NHD 3
#define HDIM 64
#define NE 4
#define NT 65
#define NCLS 100
#define DH 384
#define NTHR 768
#define NWARP 24
#define YS 196          // Y row stride (4 mod 32 -> conflict-free mma a-frags)
#define SS 196          // S row stride
#define HTS 196
#define OHS 68

typedef unsigned long long ull;

struct __align__(16) SM {
    float t[66 * DD];
    float Y[72 * YS];        // fp32 LN output; LN2's becomes tf32 bits during MoE
    float S[66 * SS];        // qkv out per head; MoE: Htf (48 x HTS u32) aliases
    float Oh[80 * OHS];      // per-head attention out (rows 65..79 zero)
    float m[72], rs[72];
    float gl[NT * NE];
    float selw[NT * 2];
    float ewt[NE * 80];
    int   seli[NT * 2];
    int   elist[NE * 80];
    int   ecnt[NE];
};

__device__ __forceinline__ float gelu_exact(float x) {
    return 0.5f * x * (1.0f + erff(x * 0.70710678118654752f));
}
__device__ __forceinline__ float dot4(float4 a, float4 b) {
    return a.x * b.x + a.y * b.y + a.z * b.z + a.w * b.w;
}
__device__ __forceinline__ unsigned to_tf32(float f) {
    unsigned u;
    asm("cvt.rna.tf32.f32 %0, %1;" : "=r"(u) : "f"(f));
    return u;
}
__device__ __forceinline__ void split2(float f, unsigned& hi, unsigned& lo) {
    hi = to_tf32(f);
    lo = to_tf32(f - __uint_as_float(hi));
}
__device__ __forceinline__ void mma_tf32(float* c, unsigned a0, unsigned a1, unsigned a2, unsigned a3,
                                         unsigned b0, unsigned b1) {
    asm volatile(
        "mma.sync.aligned.m16n8k8.row.col.f32.tf32.tf32.f32 "
        "{%0,%1,%2,%3},{%4,%5,%6,%7},{%8,%9},{%0,%1,%2,%3};"
        : "+f"(c[0]), "+f"(c[1]), "+f"(c[2]), "+f"(c[3])
        : "r"(a0), "r"(a1), "r"(a2), "r"(a3), "r"(b0), "r"(b1));
}

__device__ __forceinline__ void ln_stats(const float* __restrict__ base, int n0, int n1,
                                         float* __restrict__ m, float* __restrict__ rs) {
    int warp = threadIdx.x >> 5, lane = threadIdx.x & 31;
    for (int n = n0 + warp; n < n1; n += NWARP) {
        const float* row = base + n * DD;
        float s = 0.f;
        for (int c = lane; c < DD; c += 32) s += row[c];
#pragma unroll
        for (int o = 16; o; o >>= 1) s += __shfl_xor_sync(0xffffffffu, s, o);
        float mm = s * (1.0f / DD);
        float q = 0.f;
        for (int c = lane; c < DD; c += 32) { float d = row[c] - mm; q += d * d; }
#pragma unroll
        for (int o = 16; o; o >>= 1) q += __shfl_xor_sync(0xffffffffu, q, o);
        if (lane == 0) { m[n] = mm; rs[n] = rsqrtf(q * (1.0f / DD) + 1e-5f); }
    }
}

__global__ void __launch_bounds__(NTHR, 1) hypervit_kernel(
    const float* __restrict__ x, const float* __restrict__ conv_w, const float* __restrict__ conv_b,
    const float* __restrict__ pe_g, const float* __restrict__ pe_b,
    const float* __restrict__ cls_token, const float* __restrict__ pos_embed,
    const float* __restrict__ n1_g, const float* __restrict__ n1_b,
    const float* __restrict__ qkv_w, const float* __restrict__ temp,
    const float* __restrict__ proj_w, const float* __restrict__ proj_b,
    const float* __restrict__ n2_g, const float* __restrict__ n2_b,
    const float* __restrict__ gate_w, const float* __restrict__ gate_b,
    const float* __restrict__ e_w1, const float* __restrict__ e_b1,
    const float* __restrict__ e_w2, const float* __restrict__ e_b2,
    const float* __restrict__ attn_scale, const float* __restrict__ mlp_scale,
    const float* __restrict__ norm_g, const float* __restrict__ norm_b,
    const float* __restrict__ hc_w, const float* __restrict__ hc_b,
    const float* __restrict__ head_w, const float* __restrict__ head_b,
    float* __restrict__ out)
{
    extern __shared__ char smraw[];
    SM* sp = (SM*)smraw;
    const int b = blockIdx.x;
    const int tid = threadIdx.x;
    const int warp = tid >> 5, lane = tid & 31;
    const int l4 = lane & 3, lq = lane >> 2;
    float* t = sp->t;
    float* Y = sp->Y;
    float* S = sp->S;
    float* Oh = sp->Oh;

    // zero pad regions once
    for (int i = tid; i < 6 * YS; i += NTHR) Y[66 * YS + i] = 0.f;
    for (int i = tid; i < 15 * OHS; i += NTHR) Oh[65 * OHS + i] = 0.f;

    // ======================= patch embed =======================
    {
        float* P = Y;
        for (int i = tid; i < 64 * 48; i += NTHR) {
            int patch = i / 48, f = i % 48;
            int c = f >> 4, pi = (f >> 2) & 3, pj = f & 3;
            int ph = patch >> 3, pw = patch & 7;
            P[i] = x[((b * 3 + c) * 32 + ph * 4 + pi) * 32 + pw * 4 + pj];
        }
        __syncthreads();
        for (int task = tid; task < 64 * DD; task += NTHR) {
            int p = task / DD, c = task % DD;
            const float* w = conv_w + c * 48;
            float acc = conv_b[c];
#pragma unroll
            for (int k = 0; k < 48; k += 4) {
                float4 w4 = *(const float4*)(w + k);
                float4 p4 = *(const float4*)(P + p * 48 + k);
                acc += dot4(p4, w4);
            }
            t[(p + 1) * DD + c] = acc;
        }
        __syncthreads();
        ln_stats(t, 1, 65, sp->m, sp->rs);
        __syncthreads();
        for (int i = tid; i < 64 * DD; i += NTHR) {
            int n = 1 + i / DD, c = i % DD;
            t[n * DD + c] = (t[n * DD + c] - sp->m[n]) * sp->rs[n] * pe_g[c] + pe_b[c]
                            + pos_embed[n * DD + c];
        }
        for (int c = tid; c < DD; c += NTHR) {
            t[c] = cls_token[c] + pos_embed[c];
            t[65 * DD + c] = 0.f;
        }
    }
    __syncthreads();

    // ======================= transformer layers =======================
    for (int l = 0; l < DEPTHL; l++) {
        // ---- LN1 -> Y (fp32) ----
        ln_stats(t, 0, 65, sp->m, sp->rs);
        __syncthreads();
        for (int i = tid; i < 65 * DD; i += NTHR) {
            int n = i / DD, c = i % DD;
            Y[n * YS + c] = (t[i] - sp->m[n]) * sp->rs[n] * n1_g[l * DD + c] + n1_b[l * DD + c];
        }
        for (int c = tid; c < DD; c += NTHR) Y[65 * YS + c] = 0.f;
        __syncthreads();

        const float asc = attn_scale[l];
        const int colq = warp * 8 + lq;    // this thread's output column (0..191)

        for (int h = 0; h < NHD; h++) {
            // ===== qkv GEMM head h (split-tf32 mma, weights direct from global) =====
            {
                int sec = colq >> 6, d = colq & 63;
                const float* wq = qkv_w + ((size_t)(l * 3 + sec) * DD + h * HDIM + d) * DD;
                for (int mp = 0; mp < 2; mp++) {
                    int mt0 = mp * 3, nmt = mp ? 2 : 3;
                    float acc[3][4];
#pragma unroll
                    for (int mt = 0; mt < 3; mt++)
#pragma unroll
                        for (int i = 0; i < 4; i++) acc[mt][i] = 0.f;
                    float pb0 = wq[l4], pb1 = wq[l4 + 4];
                    for (int ko = 0; ko < 24; ko++) {
                        float nb0 = 0.f, nb1 = 0.f;
                        if (ko < 23) { nb0 = wq[(ko + 1) * 8 + l4]; nb1 = wq[(ko + 1) * 8 + l4 + 4]; }
                        unsigned bh0, bl0, bh1, bl1;
                        split2(pb0, bh0, bl0); split2(pb1, bh1, bl1);
                        int k0 = ko * 8 + l4;
#pragma unroll
                        for (int mt = 0; mt < 3; mt++) if (mt < nmt) {
                            int r0 = (mt0 + mt) * 16;
                            float a0f = Y[(r0 + lq) * YS + k0];
                            float a1f = Y[(r0 + 8 + lq) * YS + k0];
                            float a2f = Y[(r0 + lq) * YS + k0 + 4];
                            float a3f = Y[(r0 + 8 + lq) * YS + k0 + 4];
                            unsigned ah0, al0, ah1, al1, ah2, al2, ah3, al3;
                            split2(a0f, ah0, al0); split2(a1f, ah1, al1);
                            split2(a2f, ah2, al2); split2(a3f, ah3, al3);
                            mma_tf32(acc[mt], ah0, ah1, ah2, ah3, bh0, bh1);
                            mma_tf32(acc[mt], ah0, ah1, ah2, ah3, bl0, bl1);
                            mma_tf32(acc[mt], al0, al1, al2, al3, bh0, bh1);
                        }
                        pb0 = nb0; pb1 = nb1;
                    }
                    int cc = warp * 8 + 2 * l4;
#pragma unroll
                    for (int mt = 0; mt < 3; mt++) if (mt < nmt) {
                        int rA = (mt0 + mt) * 16 + lq, rB = rA + 8;
                        if (rA < 66) { S[rA * SS + cc] = acc[mt][0]; S[rA * SS + cc + 1] = acc[mt][1]; }
                        if (rB < 66) { S[rB * SS + cc] = acc[mt][2]; S[rB * SS + cc + 1] = acc[mt][3]; }
                    }
                }
            }
            __syncthreads();   // publish S

            // ===== banded attention (|i-j|<=3) -> Oh =====
            {
                float coef = 0.125f / temp[l * NHD + h];
                for (int i = warp; i < 65; i += NWARP) {
                    int jlo = (i - 3 < 0) ? 0 : i - 3;
                    int jhi = (i + 3 > 64) ? 64 : i + 3;
                    int cnt = jhi - jlo + 1;
                    float2 qv = *(const float2*)(S + i * SS + 2 * lane);
                    float sc[7];
#pragma unroll
                    for (int jj = 0; jj < 7; jj++) {
                        if (jj < cnt) {
                            float2 kv = *(const float2*)(S + (jlo + jj) * SS + 64 + 2 * lane);
                            float p = qv.x * kv.x + qv.y * kv.y;
#pragma unroll
                            for (int o = 16; o; o >>= 1) p += __shfl_xor_sync(0xffffffffu, p, o);
                            sc[jj] = p * coef;
                        }
                    }
                    float mx = sc[0];
#pragma unroll
                    for (int jj = 1; jj < 7; jj++) if (jj < cnt) mx = fmaxf(mx, sc[jj]);
                    float ssum = 0.f;
#pragma unroll
                    for (int jj = 0; jj < 7; jj++) if (jj < cnt) { sc[jj] = expf(sc[jj] - mx); ssum += sc[jj]; }
                    float inv = 1.0f / ssum;
                    float o0 = 0.f, o1 = 0.f;
#pragma unroll
                    for (int jj = 0; jj < 7; jj++) {
                        if (jj < cnt) {
                            float2 vv = *(const float2*)(S + (jlo + jj) * SS + 128 + 2 * lane);
                            o0 += sc[jj] * vv.x;
                            o1 += sc[jj] * vv.y;
                        }
                    }
                    Oh[i * OHS + 2 * lane]     = o0 * inv;
                    Oh[i * OHS + 2 * lane + 1] = o1 * inv;
                }
            }
            __syncthreads();   // publish Oh

            // ===== proj partial (k=64 of head h), split-tf32 mma =====
            {
                const float* wp = proj_w + ((size_t)l * DD + colq) * DD + h * HDIM;
                for (int mp = 0; mp < 2; mp++) {
                    int mt0 = mp * 3, nmt = mp ? 2 : 3;
                    float acc[3][4];
#pragma unroll
                    for (int mt = 0; mt < 3; mt++)
#pragma unroll
                        for (int i = 0; i < 4; i++) acc[mt][i] = 0.f;
                    float pb0 = wp[l4], pb1 = wp[l4 + 4];
                    for (int ko = 0; ko < 8; ko++) {
                        float nb0 = 0.f, nb1 = 0.f;
                        if (ko < 7) { nb0 = wp[(ko + 1) * 8 + l4]; nb1 = wp[(ko + 1) * 8 + l4 + 4]; }
                        unsigned bh0, bl0, bh1, bl1;
                        split2(pb0, bh0, bl0); split2(pb1, bh1, bl1);
                        int k0 = ko * 8 + l4;
#pragma unroll
                        for (int mt = 0; mt < 3; mt++) if (mt < nmt) {
                            int r0 = (mt0 + mt) * 16;
                            float a0f = Oh[(r0 + lq) * OHS + k0];
                            float a1f = Oh[(r0 + 8 + lq) * OHS + k0];
                            float a2f = Oh[(r0 + lq) * OHS + k0 + 4];
                            float a3f = Oh[(r0 + 8 + lq) * OHS + k0 + 4];
                            unsigned ah0, al0, ah1, al1, ah2, al2, ah3, al3;
                            split2(a0f, ah0, al0); split2(a1f, ah1, al1);
                            split2(a2f, ah2, al2); split2(a3f, ah3, al3);
                            mma_tf32(acc[mt], ah0, ah1, ah2, ah3, bh0, bh1);
                            mma_tf32(acc[mt], ah0, ah1, ah2, ah3, bl0, bl1);
                            mma_tf32(acc[mt], al0, al1, al2, al3, bh0, bh1);
                        }
                        pb0 = nb0; pb1 = nb1;
                    }
                    int cc = warp * 8 + 2 * l4;
                    float pbias0 = (h == 0) ? proj_b[l * DD + cc] : 0.f;
                    float pbias1 = (h == 0) ? proj_b[l * DD + cc + 1] : 0.f;
#pragma unroll
                    for (int mt = 0; mt < 3; mt++) if (mt < nmt) {
                        int rA = (mt0 + mt) * 16 + lq, rB = rA + 8;
                        if (rA < 66) {
                            t[rA * DD + cc]     += asc * (acc[mt][0] + pbias0);
                            t[rA * DD + cc + 1] += asc * (acc[mt][1] + pbias1);
                        }
                        if (rB < 66) {
                            t[rB * DD + cc]     += asc * (acc[mt][2] + pbias0);
                            t[rB * DD + cc + 1] += asc * (acc[mt][3] + pbias1);
                        }
                    }
                }
            }
            __syncthreads();   // t updated; S/Oh reusable
        }

        // ---- LN2 -> Y (fp32) ----
        ln_stats(t, 0, 65, sp->m, sp->rs);
        __syncthreads();
        for (int i = tid; i < 65 * DD; i += NTHR) {
            int n = i / DD, c = i % DD;
            Y[n * YS + c] = (t[i] - sp->m[n]) * sp->rs[n] * n2_g[l * DD + c] + n2_b[l * DD + c];
        }
        for (int c = tid; c < DD; c += NTHR) Y[65 * YS + c] = 0.f;
        __syncthreads();

        // ---- gating (reads fp32 Y) ----
        for (int task = tid; task < NT * NE; task += NTHR) {
            int n = task >> 2, e = task & 3;
            const float* gw = gate_w + ((size_t)l * NE + e) * DD;
            float acc = gate_b[l * NE + e];
            for (int c = 0; c < DD; c += 4) {
                float4 y4 = *(const float4*)(Y + n * YS + c);
                float4 w4 = *(const float4*)(gw + c);
                acc += dot4(y4, w4);
            }
            sp->gl[n * NE + e] = acc;
        }
        __syncthreads();
        // convert Y rows 0..65 in place to tf32; top-2 select in parallel
        for (int i = tid; i < 66 * DD; i += NTHR) {
            int n = i / DD, c = i % DD;
            ((unsigned*)Y)[n * YS + c] = to_tf32(Y[n * YS + c]);
        }
        if (tid < NT) {
            float vv[4] = { sp->gl[tid * 4 + 0], sp->gl[tid * 4 + 1],
                            sp->gl[tid * 4 + 2], sp->gl[tid * 4 + 3] };
            int i0 = 0; float bmax = vv[0];
#pragma unroll
            for (int e = 1; e < 4; e++) if (vv[e] > bmax) { bmax = vv[e]; i0 = e; }
            int i1 = -1; float b2v = -1e30f;
#pragma unroll
            for (int e = 0; e < 4; e++) if (e != i0 && vv[e] > b2v) { b2v = vv[e]; i1 = e; }
            float w1 = expf(b2v - bmax);
            float inv = 1.0f / (1.0f + w1);
            sp->seli[tid * 2 + 0] = i0;
            sp->seli[tid * 2 + 1] = i1;
            sp->selw[tid * 2 + 0] = inv;
            sp->selw[tid * 2 + 1] = w1 * inv;
        }
        __syncthreads();
        if (tid == 0) {
            float msc = mlp_scale[l];
            int cnt[4] = { 0, 0, 0, 0 };
            for (int n = 0; n < NT; n++) {
                for (int sidx = 0; sidx < 2; sidx++) {
                    int e = sp->seli[n * 2 + sidx];
                    sp->elist[e * 80 + cnt[e]] = n;
                    sp->ewt[e * 80 + cnt[e]] = sp->selw[n * 2 + sidx] * msc;
                    cnt[e]++;
                }
            }
            for (int e = 0; e < 4; e++) {
                while (cnt[e] % 16 != 0) {
                    sp->elist[e * 80 + cnt[e]] = 65;   // tf32 zero row
                    sp->ewt[e * 80 + cnt[e]] = 0.f;
                    cnt[e]++;
                }
                sp->ecnt[e] = cnt[e];
            }
        }
        __syncthreads();

        // ---- expert FFNs on tensor cores (single tf32, as R12) ----
        const unsigned* YT = (const unsigned*)Y;
        unsigned* Htf = (unsigned*)S;     // 48 x HTS (S dead during MoE)
        for (int e = 0; e < NE; e++) {
            int cnt = sp->ecnt[e];
            if (cnt == 0) continue;
            const float* w1b = e_w1 + (size_t)(l * NE + e) * DH * DD;
            const float* w2b = e_w2 + (size_t)(l * NE + e) * DD * DH;
            const float* b1p = e_b1 + (size_t)(l * NE + e) * DH;
            const float* b2p = e_b2 + (size_t)(l * NE + e) * DD;
            int base0 = e * 80;
            for (int mb = 0; mb < cnt; mb += 48) {
                int nmt = (cnt - mb) >> 4; if (nmt > 3) nmt = 3;
                int tokA[3], tokB[3];
#pragma unroll
                for (int mt = 0; mt < 3; mt++) if (mt < nmt) {
                    tokA[mt] = sp->elist[base0 + mb + mt * 16 + lq];
                    tokB[mt] = sp->elist[base0 + mb + mt * 16 + 8 + lq];
                }
                float acc2[3][4];
#pragma unroll
                for (int mt = 0; mt < 3; mt++)
#pragma unroll
                    for (int i = 0; i < 4; i++) acc2[mt][i] = 0.f;

                for (int kh = 0; kh < 2; kh++) {
                    float acc1[3][4];
#pragma unroll
                    for (int mt = 0; mt < 3; mt++)
#pragma unroll
                        for (int i = 0; i < 4; i++) acc1[mt][i] = 0.f;
                    {
                        const float* wb = w1b + (size_t)(kh * 192 + warp * 8 + lq) * DD + l4;
                        float pb0 = wb[0], pb1 = wb[4];
#pragma unroll 2
                        for (int ks = 0; ks < 24; ks++) {
                            float nb0 = 0.f, nb1 = 0.f;
                            if (ks < 23) { nb0 = wb[(ks + 1) * 8]; nb1 = wb[(ks + 1) * 8 + 4]; }
                            unsigned ub0 = to_tf32(pb0), ub1 = to_tf32(pb1);
                            int k0 = ks * 8 + l4;
#pragma unroll
                            for (int mt = 0; mt < 3; mt++) if (mt < nmt) {
                                unsigned a0 = YT[tokA[mt] * YS + k0];
                                unsigned a1 = YT[tokB[mt] * YS + k0];
                                unsigned a2 = YT[tokA[mt] * YS + k0 + 4];
                                unsigned a3 = YT[tokB[mt] * YS + k0 + 4];
                                mma_tf32(acc1[mt], a0, a1, a2, a3, ub0, ub1);
                            }
                            pb0 = nb0; pb1 = nb1;
                        }
                    }
                    {
                        int cl = warp * 8 + 2 * l4;
                        float bia0 = b1p[kh * 192 + cl], bia1 = b1p[kh * 192 + cl + 1];
#pragma unroll
                        for (int mt = 0; mt < 3; mt++) if (mt < nmt) {
                            int rA = mt * 16 + lq, rB = rA + 8;
                            Htf[rA * HTS + cl]     = to_tf32(gelu_exact(acc1[mt][0] + bia0));
                            Htf[rA * HTS + cl + 1] = to_tf32(gelu_exact(acc1[mt][1] + bia1));
                            Htf[rB * HTS + cl]     = to_tf32(gelu_exact(acc1[mt][2] + bia0));
                            Htf[rB * HTS + cl + 1] = to_tf32(gelu_exact(acc1[mt][3] + bia1));
                        }
                    }
                    __syncthreads();   // publish Htf
                    {
                        const float* wb = w2b + (size_t)(warp * 8 + lq) * DH + kh * 192 + l4;
                        float pb0 = wb[0], pb1 = wb[4];
#pragma unroll 2
                        for (int ks = 0; ks < 24; ks++) {
                            float nb0 = 0.f, nb1 = 0.f;
                            if (ks < 23) { nb0 = wb[(ks + 1) * 8]; nb1 = wb[(ks + 1) * 8 + 4]; }
                            unsigned ub0 = to_tf32(pb0), ub1 = to_tf32(pb1);
                            int k0 = ks * 8 + l4;
#pragma unroll
                            for (int mt = 0; mt < 3; mt++) if (mt < nmt) {
                                unsigned a0 = Htf[(mt * 16 + lq) * HTS + k0];
                                unsigned a1 = Htf[(mt * 16 + 8 + lq) * HTS + k0];
                                unsigned a2 = Htf[(mt * 16 + lq) * HTS + k0 + 4];
                                unsigned a3 = Htf[(mt * 16 + 8 + lq) * HTS + k0 + 4];
                                mma_tf32(acc2[mt], a0, a1, a2, a3, ub0, ub1);
                            }
                            pb0 = nb0; pb1 = nb1;
                        }
                    }
                    __syncthreads();   // Htf consumed before next kh overwrites
                }
                {
                    int c = warp * 8 + 2 * l4;
                    float bb0 = b2p[c], bb1 = b2p[c + 1];
#pragma unroll
                    for (int mt = 0; mt < 3; mt++) if (mt < nmt) {
                        int iA = base0 + mb + mt * 16 + lq, iB = iA + 8;
                        int tA = sp->elist[iA]; float wA = sp->ewt[iA];
                        int tB = sp->elist[iB]; float wB = sp->ewt[iB];
                        t[tA * DD + c]     += wA * (acc2[mt][0] + bb0);
                        t[tA * DD + c + 1] += wA * (acc2[mt][1] + bb1);
                        t[tB * DD + c]     += wB * (acc2[mt][2] + bb0);
                        t[tB * DD + c + 1] += wB * (acc2[mt][3] + bb1);
                    }
                }
                __syncthreads();
            }
        }
        __syncthreads();
    }

    // ======================= final norm + circulant head =======================
    ln_stats(t, 0, 1, sp->m, sp->rs);
    __syncthreads();
    float* cls = Y;
    for (int c = tid; c < DD; c += NTHR)
        cls[c] = (t[c] - sp->m[0]) * sp->rs[0] * norm_g[c] + norm_b[c];
    __syncthreads();
    float* HH = S;
    for (int ko = tid; ko < 2 * DD; ko += NTHR) {
        int k = ko / 96, o = ko % 96;
        float acc = hc_b[ko];
#pragma unroll
        for (int j = 0; j < 4; j++) {
            const float* w = hc_w + ((size_t)((k - j) & 3) * 96 + o) * 48;
            const float* xv = cls + j * 48;
#pragma unroll
            for (int c = 0; c < 48; c += 4) {
                float4 w4 = *(const float4*)(w + c);
                float4 x4 = *(const float4*)(xv + c);
                acc += dot4(x4, w4);
            }
        }
        HH[ko] = gelu_exact(acc);
    }
    __syncthreads();
    for (int ci = tid; ci < NCLS; ci += NTHR) {
        const float* w = head_w + (size_t)ci * (2 * DD);
        float acc = head_b[ci];
        for (int c = 0; c < 2 * DD; c += 4) {
            float4 w4 = *(const float4*)(w + c);
            float4 h4 = *(const float4*)(HH + c);
            acc += dot4(h4, w4);
        }
        out[b * NCLS + ci] = acc;
    }
}

extern "C" void kernel_launch(void* const* d_in, const int* in_sizes, int n_in,
                              void* d_out, int out_size) {
    (void)in_sizes; (void)n_in; (void)out_size;
    const float* x          = (const float*)d_in[0];
    const float* conv_w     = (const float*)d_in[1];
    const float* conv_b     = (const float*)d_in[2];
    const float* pe_g       = (const float*)d_in[3];
    const float* pe_b       = (const float*)d_in[4];
    const float* cls_token  = (const float*)d_in[5];
    const float* pos_embed  = (const float*)d_in[6];
    const float* n1_g       = (const float*)d_in[7];
    const float* n1_b       = (const float*)d_in[8];
    const float* qkv_w      = (const float*)d_in[9];
    const float* temp       = (const float*)d_in[10];
    const float* proj_w     = (const float*)d_in[11];
    const float* proj_b     = (const float*)d_in[12];
    const float* n2_g       = (const float*)d_in[13];
    const float* n2_b       = (const float*)d_in[14];
    const float* gate_w     = (const float*)d_in[15];
    const float* gate_b     = (const float*)d_in[16];
    const float* e_w1       = (const float*)d_in[17];
    const float* e_b1       = (const float*)d_in[18];
    const float* e_w2       = (const float*)d_in[19];
    const float* e_b2       = (const float*)d_in[20];
    const float* attn_scale = (const float*)d_in[21];
    const float* mlp_scale  = (const float*)d_in[22];
    const float* norm_g     = (const float*)d_in[23];
    const float* norm_b     = (const float*)d_in[24];
    const float* hc_w       = (const float*)d_in[25];
    const float* hc_b       = (const float*)d_in[26];
    const float* head_w     = (const float*)d_in[27];
    const float* head_b     = (const float*)d_in[28];

    cudaFuncSetAttribute(hypervit_kernel, cudaFuncAttributeMaxDynamicSharedMemorySize,
                         (int)sizeof(SM));
    hypervit_kernel<<<NB, NTHR, sizeof(SM)>>>(
        x, conv_w, conv_b, pe_g, pe_b, cls_token, pos_embed,
        n1_g, n1_b, qkv_w, temp, proj_w, proj_b, n2_g, n2_b,
        gate_w, gate_b, e_w1, e_b1, e_w2, e_b2,
        attn_scale, mlp_scale, norm_g, norm_b, hc_w, hc_b,
        head_w, head_b, (float*)d_out);
}

// round 15
// speedup vs baseline: 1.0852x; 1.0852x over previous
#include <cuda_runtime.h>
#include <math.h>

#define NB 128
#define DD 192
#define DEPTHL 12
#define NHD 3
#define HDIM 64
#define NE 4
#define NT 65
#define NCLS 100
#define DH 384
#define NTHR 768
#define NWARP 24
#define YS 196          // Yhi/Ylo row stride (4 mod 32 -> conflict-free mma a-frags)
#define SSS 192         // S row stride
#define HTS 196
#define OHS 68

struct __align__(16) SM {
    float t[66 * DD];
    float Yhi[66 * YS];      // tf32-hi bits after LN1; fp32 then tf32 after LN2
    float Ylo[66 * YS];      // tf32-lo bits after LN1 (qkv only)
    float S[66 * SSS];       // qkv out (fp32); MoE Htf aliases (48 x HTS)
    float Oh[72 * OHS];      // attention out fp32 (rows 65..71 zero)
    float m[72], rs[72];
    float gl[NT * NE];
    float selw[NT * 2];
    float ewt[NE * 80];
    int   seli[NT * 2];
    int   elist[NE * 80];
    int   ecnt[NE];
};

__device__ __forceinline__ float gelu_exact(float x) {
    return 0.5f * x * (1.0f + erff(x * 0.70710678118654752f));
}
__device__ __forceinline__ float dot4(float4 a, float4 b) {
    return a.x * b.x + a.y * b.y + a.z * b.z + a.w * b.w;
}
__device__ __forceinline__ unsigned to_tf32(float f) {
    unsigned u;
    asm("cvt.rna.tf32.f32 %0, %1;" : "=r"(u) : "f"(f));
    return u;
}
__device__ __forceinline__ void split2(float f, unsigned& hi, unsigned& lo) {
    hi = to_tf32(f);
    lo = to_tf32(f - __uint_as_float(hi));
}
__device__ __forceinline__ void mma_tf32(float* c, unsigned a0, unsigned a1, unsigned a2, unsigned a3,
                                         unsigned b0, unsigned b1) {
    asm volatile(
        "mma.sync.aligned.m16n8k8.row.col.f32.tf32.tf32.f32 "
        "{%0,%1,%2,%3},{%4,%5,%6,%7},{%8,%9},{%0,%1,%2,%3};"
        : "+f"(c[0]), "+f"(c[1]), "+f"(c[2]), "+f"(c[3])
        : "r"(a0), "r"(a1), "r"(a2), "r"(a3), "r"(b0), "r"(b1));
}

__device__ __forceinline__ void ln_stats(const float* __restrict__ base, int n0, int n1,
                                         float* __restrict__ m, float* __restrict__ rs) {
    int warp = threadIdx.x >> 5, lane = threadIdx.x & 31;
    for (int n = n0 + warp; n < n1; n += NWARP) {
        const float* row = base + n * DD;
        float s = 0.f;
        for (int c = lane; c < DD; c += 32) s += row[c];
#pragma unroll
        for (int o = 16; o; o >>= 1) s += __shfl_xor_sync(0xffffffffu, s, o);
        float mm = s * (1.0f / DD);
        float q = 0.f;
        for (int c = lane; c < DD; c += 32) { float d = row[c] - mm; q += d * d; }
#pragma unroll
        for (int o = 16; o; o >>= 1) q += __shfl_xor_sync(0xffffffffu, q, o);
        if (lane == 0) { m[n] = mm; rs[n] = rsqrtf(q * (1.0f / DD) + 1e-5f); }
    }
}

__global__ void __launch_bounds__(NTHR, 1) hypervit_kernel(
    const float* __restrict__ x, const float* __restrict__ conv_w, const float* __restrict__ conv_b,
    const float* __restrict__ pe_g, const float* __restrict__ pe_b,
    const float* __restrict__ cls_token, const float* __restrict__ pos_embed,
    const float* __restrict__ n1_g, const float* __restrict__ n1_b,
    const float* __restrict__ qkv_w, const float* __restrict__ temp,
    const float* __restrict__ proj_w, const float* __restrict__ proj_b,
    const float* __restrict__ n2_g, const float* __restrict__ n2_b,
    const float* __restrict__ gate_w, const float* __restrict__ gate_b,
    const float* __restrict__ e_w1, const float* __restrict__ e_b1,
    const float* __restrict__ e_w2, const float* __restrict__ e_b2,
    const float* __restrict__ attn_scale, const float* __restrict__ mlp_scale,
    const float* __restrict__ norm_g, const float* __restrict__ norm_b,
    const float* __restrict__ hc_w, const float* __restrict__ hc_b,
    const float* __restrict__ head_w, const float* __restrict__ head_b,
    float* __restrict__ out)
{
    extern __shared__ char smraw[];
    SM* sp = (SM*)smraw;
    const int b = blockIdx.x;
    const int tid = threadIdx.x;
    const int warp = tid >> 5, lane = tid & 31;
    const int l4 = lane & 3, lq = lane >> 2;
    float* t = sp->t;
    float* Yhi = sp->Yhi;
    float* Ylo = sp->Ylo;
    float* S = sp->S;
    float* Oh = sp->Oh;

    for (int i = tid; i < 7 * OHS; i += NTHR) Oh[65 * OHS + i] = 0.f;

    // ======================= patch embed =======================
    {
        float* P = Yhi;
        for (int i = tid; i < 64 * 48; i += NTHR) {
            int patch = i / 48, f = i % 48;
            int c = f >> 4, pi = (f >> 2) & 3, pj = f & 3;
            int ph = patch >> 3, pw = patch & 7;
            P[i] = x[((b * 3 + c) * 32 + ph * 4 + pi) * 32 + pw * 4 + pj];
        }
        __syncthreads();
        for (int task = tid; task < 64 * DD; task += NTHR) {
            int p = task / DD, c = task % DD;
            const float* w = conv_w + c * 48;
            float acc = conv_b[c];
#pragma unroll
            for (int k = 0; k < 48; k += 4) {
                float4 w4 = *(const float4*)(w + k);
                float4 p4 = *(const float4*)(P + p * 48 + k);
                acc += dot4(p4, w4);
            }
            t[(p + 1) * DD + c] = acc;
        }
        __syncthreads();
        ln_stats(t, 1, 65, sp->m, sp->rs);
        __syncthreads();
        for (int i = tid; i < 64 * DD; i += NTHR) {
            int n = 1 + i / DD, c = i % DD;
            t[n * DD + c] = (t[n * DD + c] - sp->m[n]) * sp->rs[n] * pe_g[c] + pe_b[c]
                            + pos_embed[n * DD + c];
        }
        for (int c = tid; c < DD; c += NTHR) {
            t[c] = cls_token[c] + pos_embed[c];
            t[65 * DD + c] = 0.f;
        }
    }
    __syncthreads();

    // ======================= transformer layers =======================
    for (int l = 0; l < DEPTHL; l++) {
        // ---- LN1 -> Yhi/Ylo (tf32 hi/lo bits) ----
        ln_stats(t, 0, 65, sp->m, sp->rs);
        __syncthreads();
        for (int i = tid; i < 65 * DD; i += NTHR) {
            int n = i / DD, c = i % DD;
            float v = (t[i] - sp->m[n]) * sp->rs[n] * n1_g[l * DD + c] + n1_b[l * DD + c];
            unsigned hi, lo;
            split2(v, hi, lo);
            ((unsigned*)Yhi)[n * YS + c] = hi;
            ((unsigned*)Ylo)[n * YS + c] = lo;
        }
        for (int c = tid; c < DD; c += NTHR) { Yhi[65 * YS + c] = 0.f; Ylo[65 * YS + c] = 0.f; }
        __syncthreads();

        const float asc = attn_scale[l];
        const int colq = warp * 8 + lq;    // output column (0..191)
        const unsigned* Yh = (const unsigned*)Yhi;
        const unsigned* Yl = (const unsigned*)Ylo;

        for (int h = 0; h < NHD; h++) {
            // ===== qkv GEMM head h: 3-term split tf32, zero in-loop A-CVT =====
            {
                int sec = colq >> 6, d = colq & 63;
                const float* wq = qkv_w + ((size_t)(l * 3 + sec) * DD + h * HDIM + d) * DD;
                float acc[5][4];
#pragma unroll
                for (int mt = 0; mt < 5; mt++)
#pragma unroll
                    for (int i = 0; i < 4; i++) acc[mt][i] = 0.f;
                float pb0 = wq[l4], pb1 = wq[l4 + 4];
                for (int ko = 0; ko < 24; ko++) {
                    float nb0 = 0.f, nb1 = 0.f;
                    if (ko < 23) { nb0 = wq[(ko + 1) * 8 + l4]; nb1 = wq[(ko + 1) * 8 + l4 + 4]; }
                    unsigned bh0, bl0, bh1, bl1;
                    split2(pb0, bh0, bl0); split2(pb1, bh1, bl1);
                    int k0 = ko * 8 + l4;
#pragma unroll
                    for (int mt = 0; mt < 5; mt++) {
                        int r0 = mt * 16;
                        unsigned ah0 = Yh[(r0 + lq) * YS + k0];
                        unsigned ah1 = Yh[(r0 + 8 + lq) * YS + k0];
                        unsigned ah2 = Yh[(r0 + lq) * YS + k0 + 4];
                        unsigned ah3 = Yh[(r0 + 8 + lq) * YS + k0 + 4];
                        unsigned al0 = Yl[(r0 + lq) * YS + k0];
                        unsigned al1 = Yl[(r0 + 8 + lq) * YS + k0];
                        unsigned al2 = Yl[(r0 + lq) * YS + k0 + 4];
                        unsigned al3 = Yl[(r0 + 8 + lq) * YS + k0 + 4];
                        mma_tf32(acc[mt], ah0, ah1, ah2, ah3, bh0, bh1);
                        mma_tf32(acc[mt], ah0, ah1, ah2, ah3, bl0, bl1);
                        mma_tf32(acc[mt], al0, al1, al2, al3, bh0, bh1);
                    }
                    pb0 = nb0; pb1 = nb1;
                }
                int cc = warp * 8 + 2 * l4;
#pragma unroll
                for (int mt = 0; mt < 5; mt++) {
                    int rA = mt * 16 + lq, rB = rA + 8;
                    if (rA < 66) { S[rA * SSS + cc] = acc[mt][0]; S[rA * SSS + cc + 1] = acc[mt][1]; }
                    if (rB < 66) { S[rB * SSS + cc] = acc[mt][2]; S[rB * SSS + cc + 1] = acc[mt][3]; }
                }
            }
            __syncthreads();   // publish S

            // ===== banded attention (|i-j|<=3) -> Oh (fp32) =====
            {
                float coef = 0.125f / temp[l * NHD + h];
                for (int i = warp; i < 65; i += NWARP) {
                    int jlo = (i - 3 < 0) ? 0 : i - 3;
                    int jhi = (i + 3 > 64) ? 64 : i + 3;
                    int cnt = jhi - jlo + 1;
                    float2 qv = *(const float2*)(S + i * SSS + 2 * lane);
                    float sc[7];
#pragma unroll
                    for (int jj = 0; jj < 7; jj++) {
                        if (jj < cnt) {
                            float2 kv = *(const float2*)(S + (jlo + jj) * SSS + 64 + 2 * lane);
                            float p = qv.x * kv.x + qv.y * kv.y;
#pragma unroll
                            for (int o = 16; o; o >>= 1) p += __shfl_xor_sync(0xffffffffu, p, o);
                            sc[jj] = p * coef;
                        }
                    }
                    float mx = sc[0];
#pragma unroll
                    for (int jj = 1; jj < 7; jj++) if (jj < cnt) mx = fmaxf(mx, sc[jj]);
                    float ssum = 0.f;
#pragma unroll
                    for (int jj = 0; jj < 7; jj++) if (jj < cnt) { sc[jj] = expf(sc[jj] - mx); ssum += sc[jj]; }
                    float inv = 1.0f / ssum;
                    float o0 = 0.f, o1 = 0.f;
#pragma unroll
                    for (int jj = 0; jj < 7; jj++) {
                        if (jj < cnt) {
                            float2 vv = *(const float2*)(S + (jlo + jj) * SSS + 128 + 2 * lane);
                            o0 += sc[jj] * vv.x;
                            o1 += sc[jj] * vv.y;
                        }
                    }
                    Oh[i * OHS + 2 * lane]     = o0 * inv;
                    Oh[i * OHS + 2 * lane + 1] = o1 * inv;
                }
            }
            __syncthreads();   // publish Oh

            // ===== proj partial (k=64): 3-term split tf32, in-loop A-split =====
            {
                const float* wp = proj_w + ((size_t)l * DD + colq) * DD + h * HDIM;
                float acc[5][4];
#pragma unroll
                for (int mt = 0; mt < 5; mt++)
#pragma unroll
                    for (int i = 0; i < 4; i++) acc[mt][i] = 0.f;
                float pb0 = wp[l4], pb1 = wp[l4 + 4];
                for (int ko = 0; ko < 8; ko++) {
                    float nb0 = 0.f, nb1 = 0.f;
                    if (ko < 7) { nb0 = wp[(ko + 1) * 8 + l4]; nb1 = wp[(ko + 1) * 8 + l4 + 4]; }
                    unsigned bh0, bl0, bh1, bl1;
                    split2(pb0, bh0, bl0); split2(pb1, bh1, bl1);
                    int k0 = ko * 8 + l4;
#pragma unroll
                    for (int mt = 0; mt < 5; mt++) {
                        int r0 = mt * 16;
                        float a0f = Oh[(r0 + lq) * OHS + k0];
                        float a1f = Oh[(r0 + 8 + lq) * OHS + k0];
                        float a2f = Oh[(r0 + lq) * OHS + k0 + 4];
                        float a3f = Oh[(r0 + 8 + lq) * OHS + k0 + 4];
                        unsigned ah0, al0, ah1, al1, ah2, al2, ah3, al3;
                        split2(a0f, ah0, al0); split2(a1f, ah1, al1);
                        split2(a2f, ah2, al2); split2(a3f, ah3, al3);
                        mma_tf32(acc[mt], ah0, ah1, ah2, ah3, bh0, bh1);
                        mma_tf32(acc[mt], ah0, ah1, ah2, ah3, bl0, bl1);
                        mma_tf32(acc[mt], al0, al1, al2, al3, bh0, bh1);
                    }
                    pb0 = nb0; pb1 = nb1;
                }
                int cc = warp * 8 + 2 * l4;
                float pbias0 = (h == 0) ? proj_b[l * DD + cc] : 0.f;
                float pbias1 = (h == 0) ? proj_b[l * DD + cc + 1] : 0.f;
#pragma unroll
                for (int mt = 0; mt < 5; mt++) {
                    int rA = mt * 16 + lq, rB = rA + 8;
                    if (rA < 66) {
                        t[rA * DD + cc]     += asc * (acc[mt][0] + pbias0);
                        t[rA * DD + cc + 1] += asc * (acc[mt][1] + pbias1);
                    }
                    if (rB < 66) {
                        t[rB * DD + cc]     += asc * (acc[mt][2] + pbias0);
                        t[rB * DD + cc + 1] += asc * (acc[mt][3] + pbias1);
                    }
                }
            }
            __syncthreads();   // t updated; S/Oh reusable
        }

        // ---- LN2 -> Yhi (fp32 for gating) ----
        ln_stats(t, 0, 65, sp->m, sp->rs);
        __syncthreads();
        for (int i = tid; i < 65 * DD; i += NTHR) {
            int n = i / DD, c = i % DD;
            Yhi[n * YS + c] = (t[i] - sp->m[n]) * sp->rs[n] * n2_g[l * DD + c] + n2_b[l * DD + c];
        }
        for (int c = tid; c < DD; c += NTHR) Yhi[65 * YS + c] = 0.f;
        __syncthreads();

        // ---- gating (fp32 Yhi) ----
        for (int task = tid; task < NT * NE; task += NTHR) {
            int n = task >> 2, e = task & 3;
            const float* gw = gate_w + ((size_t)l * NE + e) * DD;
            float acc = gate_b[l * NE + e];
            for (int c = 0; c < DD; c += 4) {
                float4 y4 = *(const float4*)(Yhi + n * YS + c);
                float4 w4 = *(const float4*)(gw + c);
                acc += dot4(y4, w4);
            }
            sp->gl[n * NE + e] = acc;
        }
        __syncthreads();
        // convert Yhi in place to tf32; top-2 select in parallel
        for (int i = tid; i < 66 * DD; i += NTHR) {
            int n = i / DD, c = i % DD;
            ((unsigned*)Yhi)[n * YS + c] = to_tf32(Yhi[n * YS + c]);
        }
        if (tid < NT) {
            float vv[4] = { sp->gl[tid * 4 + 0], sp->gl[tid * 4 + 1],
                            sp->gl[tid * 4 + 2], sp->gl[tid * 4 + 3] };
            int i0 = 0; float bmax = vv[0];
#pragma unroll
            for (int e = 1; e < 4; e++) if (vv[e] > bmax) { bmax = vv[e]; i0 = e; }
            int i1 = -1; float b2v = -1e30f;
#pragma unroll
            for (int e = 0; e < 4; e++) if (e != i0 && vv[e] > b2v) { b2v = vv[e]; i1 = e; }
            float w1 = expf(b2v - bmax);
            float inv = 1.0f / (1.0f + w1);
            sp->seli[tid * 2 + 0] = i0;
            sp->seli[tid * 2 + 1] = i1;
            sp->selw[tid * 2 + 0] = inv;
            sp->selw[tid * 2 + 1] = w1 * inv;
        }
        __syncthreads();
        if (tid == 0) {
            float msc = mlp_scale[l];
            int cnt[4] = { 0, 0, 0, 0 };
            for (int n = 0; n < NT; n++) {
                for (int sidx = 0; sidx < 2; sidx++) {
                    int e = sp->seli[n * 2 + sidx];
                    sp->elist[e * 80 + cnt[e]] = n;
                    sp->ewt[e * 80 + cnt[e]] = sp->selw[n * 2 + sidx] * msc;
                    cnt[e]++;
                }
            }
            for (int e = 0; e < 4; e++) {
                while (cnt[e] % 16 != 0) {
                    sp->elist[e * 80 + cnt[e]] = 65;   // tf32 zero row
                    sp->ewt[e * 80 + cnt[e]] = 0.f;
                    cnt[e]++;
                }
                sp->ecnt[e] = cnt[e];
            }
        }
        __syncthreads();

        // ---- expert FFNs on tensor cores (single tf32, as R12) ----
        const unsigned* YT = (const unsigned*)Yhi;
        unsigned* Htf = (unsigned*)S;
        for (int e = 0; e < NE; e++) {
            int cnt = sp->ecnt[e];
            if (cnt == 0) continue;
            const float* w1b = e_w1 + (size_t)(l * NE + e) * DH * DD;
            const float* w2b = e_w2 + (size_t)(l * NE + e) * DD * DH;
            const float* b1p = e_b1 + (size_t)(l * NE + e) * DH;
            const float* b2p = e_b2 + (size_t)(l * NE + e) * DD;
            int base0 = e * 80;
            for (int mb = 0; mb < cnt; mb += 48) {
                int nmt = (cnt - mb) >> 4; if (nmt > 3) nmt = 3;
                int tokA[3], tokB[3];
#pragma unroll
                for (int mt = 0; mt < 3; mt++) if (mt < nmt) {
                    tokA[mt] = sp->elist[base0 + mb + mt * 16 + lq];
                    tokB[mt] = sp->elist[base0 + mb + mt * 16 + 8 + lq];
                }
                float acc2[3][4];
#pragma unroll
                for (int mt = 0; mt < 3; mt++)
#pragma unroll
                    for (int i = 0; i < 4; i++) acc2[mt][i] = 0.f;

                for (int kh = 0; kh < 2; kh++) {
                    float acc1[3][4];
#pragma unroll
                    for (int mt = 0; mt < 3; mt++)
#pragma unroll
                        for (int i = 0; i < 4; i++) acc1[mt][i] = 0.f;
                    {
                        const float* wb = w1b + (size_t)(kh * 192 + warp * 8 + lq) * DD + l4;
                        float pb0 = wb[0], pb1 = wb[4];
#pragma unroll 2
                        for (int ks = 0; ks < 24; ks++) {
                            float nb0 = 0.f, nb1 = 0.f;
                            if (ks < 23) { nb0 = wb[(ks + 1) * 8]; nb1 = wb[(ks + 1) * 8 + 4]; }
                            unsigned ub0 = to_tf32(pb0), ub1 = to_tf32(pb1);
                            int k0 = ks * 8 + l4;
#pragma unroll
                            for (int mt = 0; mt < 3; mt++) if (mt < nmt) {
                                unsigned a0 = YT[tokA[mt] * YS + k0];
                                unsigned a1 = YT[tokB[mt] * YS + k0];
                                unsigned a2 = YT[tokA[mt] * YS + k0 + 4];
                                unsigned a3 = YT[tokB[mt] * YS + k0 + 4];
                                mma_tf32(acc1[mt], a0, a1, a2, a3, ub0, ub1);
                            }
                            pb0 = nb0; pb1 = nb1;
                        }
                    }
                    {
                        int cl = warp * 8 + 2 * l4;
                        float bia0 = b1p[kh * 192 + cl], bia1 = b1p[kh * 192 + cl + 1];
#pragma unroll
                        for (int mt = 0; mt < 3; mt++) if (mt < nmt) {
                            int rA = mt * 16 + lq, rB = rA + 8;
                            Htf[rA * HTS + cl]     = to_tf32(gelu_exact(acc1[mt][0] + bia0));
                            Htf[rA * HTS + cl + 1] = to_tf32(gelu_exact(acc1[mt][1] + bia1));
                            Htf[rB * HTS + cl]     = to_tf32(gelu_exact(acc1[mt][2] + bia0));
                            Htf[rB * HTS + cl + 1] = to_tf32(gelu_exact(acc1[mt][3] + bia1));
                        }
                    }
                    __syncthreads();
                    {
                        const float* wb = w2b + (size_t)(warp * 8 + lq) * DH + kh * 192 + l4;
                        float pb0 = wb[0], pb1 = wb[4];
#pragma unroll 2
                        for (int ks = 0; ks < 24; ks++) {
                            float nb0 = 0.f, nb1 = 0.f;
                            if (ks < 23) { nb0 = wb[(ks + 1) * 8]; nb1 = wb[(ks + 1) * 8 + 4]; }
                            unsigned ub0 = to_tf32(pb0), ub1 = to_tf32(pb1);
                            int k0 = ks * 8 + l4;
#pragma unroll
                            for (int mt = 0; mt < 3; mt++) if (mt < nmt) {
                                unsigned a0 = Htf[(mt * 16 + lq) * HTS + k0];
                                unsigned a1 = Htf[(mt * 16 + 8 + lq) * HTS + k0];
                                unsigned a2 = Htf[(mt * 16 + lq) * HTS + k0 + 4];
                                unsigned a3 = Htf[(mt * 16 + 8 + lq) * HTS + k0 + 4];
                                mma_tf32(acc2[mt], a0, a1, a2, a3, ub0, ub1);
                            }
                            pb0 = nb0; pb1 = nb1;
                        }
                    }
                    __syncthreads();
                }
                {
                    int c = warp * 8 + 2 * l4;
                    float bb0 = b2p[c], bb1 = b2p[c + 1];
#pragma unroll
                    for (int mt = 0; mt < 3; mt++) if (mt < nmt) {
                        int iA = base0 + mb + mt * 16 + lq, iB = iA + 8;
                        int tA = sp->elist[iA]; float wA = sp->ewt[iA];
                        int tB = sp->elist[iB]; float wB = sp->ewt[iB];
                        t[tA * DD + c]     += wA * (acc2[mt][0] + bb0);
                        t[tA * DD + c + 1] += wA * (acc2[mt][1] + bb1);
                        t[tB * DD + c]     += wB * (acc2[mt][2] + bb0);
                        t[tB * DD + c + 1] += wB * (acc2[mt][3] + bb1);
                    }
                }
                __syncthreads();
            }
        }
        __syncthreads();
    }

    // ======================= final norm + circulant head =======================
    ln_stats(t, 0, 1, sp->m, sp->rs);
    __syncthreads();
    float* cls = Yhi;
    for (int c = tid; c < DD; c += NTHR)
        cls[c] = (t[c] - sp->m[0]) * sp->rs[0] * norm_g[c] + norm_b[c];
    __syncthreads();
    float* HH = S;
    for (int ko = tid; ko < 2 * DD; ko += NTHR) {
        int k = ko / 96, o = ko % 96;
        float acc = hc_b[ko];
#pragma unroll
        for (int j = 0; j < 4; j++) {
            const float* w = hc_w + ((size_t)((k - j) & 3) * 96 + o) * 48;
            const float* xv = cls + j * 48;
#pragma unroll
            for (int c = 0; c < 48; c += 4) {
                float4 w4 = *(const float4*)(w + c);
                float4 x4 = *(const float4*)(xv + c);
                acc += dot4(x4, w4);
            }
        }
        HH[ko] = gelu_exact(acc);
    }
    __syncthreads();
    for (int ci = tid; ci < NCLS; ci += NTHR) {
        const float* w = head_w + (size_t)ci * (2 * DD);
        float acc = head_b[ci];
        for (int c = 0; c < 2 * DD; c += 4) {
            float4 w4 = *(const float4*)(w + c);
            float4 h4 = *(const float4*)(HH + c);
            acc += dot4(h4, w4);
        }
        out[b * NCLS + ci] = acc;
    }
}

extern "C" void kernel_launch(void* const* d_in, const int* in_sizes, int n_in,
                              void* d_out, int out_size) {
    (void)in_sizes; (void)n_in; (void)out_size;
    const float* x          = (const float*)d_in[0];
    const float* conv_w     = (const float*)d_in[1];
    const float* conv_b     = (const float*)d_in[2];
    const float* pe_g       = (const float*)d_in[3];
    const float* pe_b       = (const float*)d_in[4];
    const float* cls_token  = (const float*)d_in[5];
    const float* pos_embed  = (const float*)d_in[6];
    const float* n1_g       = (const float*)d_in[7];
    const float* n1_b       = (const float*)d_in[8];
    const float* qkv_w      = (const float*)d_in[9];
    const float* temp       = (const float*)d_in[10];
    const float* proj_w     = (const float*)d_in[11];
    const float* proj_b     = (const float*)d_in[12];
    const float* n2_g       = (const float*)d_in[13];
    const float* n2_b       = (const float*)d_in[14];
    const float* gate_w     = (const float*)d_in[15];
    const float* gate_b     = (const float*)d_in[16];
    const float* e_w1       = (const float*)d_in[17];
    const float* e_b1       = (const float*)d_in[18];
    const float* e_w2       = (const float*)d_in[19];
    const float* e_b2       = (const float*)d_in[20];
    const float* attn_scale = (const float*)d_in[21];
    const float* mlp_scale  = (const float*)d_in[22];
    const float* norm_g     = (const float*)d_in[23];
    const float* norm_b     = (const float*)d_in[24];
    const float* hc_w       = (const float*)d_in[25];
    const float* hc_b       = (const float*)d_in[26];
    const float* head_w     = (const float*)d_in[27];
    const float* head_b     = (const float*)d_in[28];

    cudaFuncSetAttribute(hypervit_kernel, cudaFuncAttributeMaxDynamicSharedMemorySize,
                         (int)sizeof(SM));
    hypervit_kernel<<<NB, NTHR, sizeof(SM)>>>(
        x, conv_w, conv_b, pe_g, pe_b, cls_token, pos_embed,
        n1_g, n1_b, qkv_w, temp, proj_w, proj_b, n2_g, n2_b,
        gate_w, gate_b, e_w1, e_b1, e_w2, e_b2,
        attn_scale, mlp_scale, norm_g, norm_b, hc_w, hc_b,
        head_w, head_b, (float*)d_out);
}

// round 16
// speedup vs baseline: 1.2452x; 1.1474x over previous
#include <cuda_runtime.h>
#include <math.h>

#define NB 128
#define DD 192
#define DEPTHL 12
#define NHD 3
#define HDIM 64
#define NE 4
#define NT 65
#define NCLS 100
#define DH 384
#define NTHR 768
#define NWARP 24
#define YS 196          // MoE fp32/tf32 Y row stride
#define YPS 100         // packed bf16 Y row stride (u32 words; 96 used)
#define OPS 36          // packed bf16 Oh row stride (32 used)
#define SSS 192         // S row stride
#define HTS 196

struct __align__(16) SM {
    float t[66 * DD];
    float S[66 * SSS];        // qkv out fp32; MoE Htf aliases (48*HTS)
    unsigned YU[16000];       // LN1: Yhi[0,8000) Ylo[8000,16000) as 80xYPS; LN2/MoE: fp32/tf32 66xYS
    unsigned OhU[2 * 80 * OPS];  // Ohh [0,2880) / Ohl [2880,5760)
    float m[72], rs[72];
    float gl[NT * NE];
    float selw[NT * 2];
    float ewt[NE * 80];
    int   seli[NT * 2];
    int   elist[NE * 80];
    int   ecnt[NE];
};

__device__ __forceinline__ float gelu_exact(float x) {
    return 0.5f * x * (1.0f + erff(x * 0.70710678118654752f));
}
__device__ __forceinline__ float dot4(float4 a, float4 b) {
    return a.x * b.x + a.y * b.y + a.z * b.z + a.w * b.w;
}
__device__ __forceinline__ unsigned to_tf32(float f) {
    unsigned u;
    asm("cvt.rna.tf32.f32 %0, %1;" : "=r"(u) : "f"(f));
    return u;
}
__device__ __forceinline__ void splitbf(float f, float& hi, float& lo) {
    hi = __uint_as_float(__float_as_uint(f) & 0xffff0000u);   // truncate: exact bf16
    lo = f - hi;                                              // exact remainder
}
__device__ __forceinline__ unsigned packbf(float lo_v, float hi_v) {  // lo_v->low half
    unsigned r;
    asm("cvt.rn.bf16x2.f32 %0, %1, %2;" : "=r"(r) : "f"(hi_v), "f"(lo_v));
    return r;
}
__device__ __forceinline__ void mma_bf16(float* c, unsigned a0, unsigned a1, unsigned a2, unsigned a3,
                                         unsigned b0, unsigned b1) {
    asm volatile(
        "mma.sync.aligned.m16n8k16.row.col.f32.bf16.bf16.f32 "
        "{%0,%1,%2,%3},{%4,%5,%6,%7},{%8,%9},{%0,%1,%2,%3};"
        : "+f"(c[0]), "+f"(c[1]), "+f"(c[2]), "+f"(c[3])
        : "r"(a0), "r"(a1), "r"(a2), "r"(a3), "r"(b0), "r"(b1));
}
__device__ __forceinline__ void mma_tf32(float* c, unsigned a0, unsigned a1, unsigned a2, unsigned a3,
                                         unsigned b0, unsigned b1) {
    asm volatile(
        "mma.sync.aligned.m16n8k8.row.col.f32.tf32.tf32.f32 "
        "{%0,%1,%2,%3},{%4,%5,%6,%7},{%8,%9},{%0,%1,%2,%3};"
        : "+f"(c[0]), "+f"(c[1]), "+f"(c[2]), "+f"(c[3])
        : "r"(a0), "r"(a1), "r"(a2), "r"(a3), "r"(b0), "r"(b1));
}

__device__ __forceinline__ void ln_stats(const float* __restrict__ base, int n0, int n1,
                                         float* __restrict__ m, float* __restrict__ rs) {
    int warp = threadIdx.x >> 5, lane = threadIdx.x & 31;
    for (int n = n0 + warp; n < n1; n += NWARP) {
        const float* row = base + n * DD;
        float s = 0.f;
        for (int c = lane; c < DD; c += 32) s += row[c];
#pragma unroll
        for (int o = 16; o; o >>= 1) s += __shfl_xor_sync(0xffffffffu, s, o);
        float mm = s * (1.0f / DD);
        float q = 0.f;
        for (int c = lane; c < DD; c += 32) { float d = row[c] - mm; q += d * d; }
#pragma unroll
        for (int o = 16; o; o >>= 1) q += __shfl_xor_sync(0xffffffffu, q, o);
        if (lane == 0) { m[n] = mm; rs[n] = rsqrtf(q * (1.0f / DD) + 1e-5f); }
    }
}

__global__ void __launch_bounds__(NTHR, 1) hypervit_kernel(
    const float* __restrict__ x, const float* __restrict__ conv_w, const float* __restrict__ conv_b,
    const float* __restrict__ pe_g, const float* __restrict__ pe_b,
    const float* __restrict__ cls_token, const float* __restrict__ pos_embed,
    const float* __restrict__ n1_g, const float* __restrict__ n1_b,
    const float* __restrict__ qkv_w, const float* __restrict__ temp,
    const float* __restrict__ proj_w, const float* __restrict__ proj_b,
    const float* __restrict__ n2_g, const float* __restrict__ n2_b,
    const float* __restrict__ gate_w, const float* __restrict__ gate_b,
    const float* __restrict__ e_w1, const float* __restrict__ e_b1,
    const float* __restrict__ e_w2, const float* __restrict__ e_b2,
    const float* __restrict__ attn_scale, const float* __restrict__ mlp_scale,
    const float* __restrict__ norm_g, const float* __restrict__ norm_b,
    const float* __restrict__ hc_w, const float* __restrict__ hc_b,
    const float* __restrict__ head_w, const float* __restrict__ head_b,
    float* __restrict__ out)
{
    extern __shared__ char smraw[];
    SM* sp = (SM*)smraw;
    const int b = blockIdx.x;
    const int tid = threadIdx.x;
    const int warp = tid >> 5, lane = tid & 31;
    const int l4 = lane & 3, lq = lane >> 2;
    float* t = sp->t;
    float* S = sp->S;
    unsigned* Yh = sp->YU;              // 80 x YPS
    unsigned* Yl = sp->YU + 8000;       // 80 x YPS
    float* Yf = (float*)sp->YU;         // LN2 fp32 view, 66 x YS
    unsigned* Ohh = sp->OhU;            // 80 x OPS
    unsigned* Ohl = sp->OhU + 80 * OPS;

    // ======================= patch embed =======================
    {
        float* P = (float*)sp->YU;
        for (int i = tid; i < 64 * 48; i += NTHR) {
            int patch = i / 48, f = i % 48;
            int c = f >> 4, pi = (f >> 2) & 3, pj = f & 3;
            int ph = patch >> 3, pw = patch & 7;
            P[i] = x[((b * 3 + c) * 32 + ph * 4 + pi) * 32 + pw * 4 + pj];
        }
        __syncthreads();
        for (int task = tid; task < 64 * DD; task += NTHR) {
            int p = task / DD, c = task % DD;
            const float* w = conv_w + c * 48;
            float acc = conv_b[c];
#pragma unroll
            for (int k = 0; k < 48; k += 4) {
                float4 w4 = *(const float4*)(w + k);
                float4 p4 = *(const float4*)(P + p * 48 + k);
                acc += dot4(p4, w4);
            }
            t[(p + 1) * DD + c] = acc;
        }
        __syncthreads();
        ln_stats(t, 1, 65, sp->m, sp->rs);
        __syncthreads();
        for (int i = tid; i < 64 * DD; i += NTHR) {
            int n = 1 + i / DD, c = i % DD;
            t[n * DD + c] = (t[n * DD + c] - sp->m[n]) * sp->rs[n] * pe_g[c] + pe_b[c]
                            + pos_embed[n * DD + c];
        }
        for (int c = tid; c < DD; c += NTHR) {
            t[c] = cls_token[c] + pos_embed[c];
            t[65 * DD + c] = 0.f;
        }
    }
    __syncthreads();

    // ======================= transformer layers =======================
    for (int l = 0; l < DEPTHL; l++) {
        // ---- LN1 -> packed bf16 hi/lo Y ----
        ln_stats(t, 0, 65, sp->m, sp->rs);
        __syncthreads();
        for (int i = tid; i < 65 * 96; i += NTHR) {
            int n = i / 96, j = i - n * 96;
            float2 tv = *(const float2*)(t + n * DD + 2 * j);
            float2 g2 = *(const float2*)(n1_g + l * DD + 2 * j);
            float2 b2 = *(const float2*)(n1_b + l * DD + 2 * j);
            float mm = sp->m[n], rr = sp->rs[n];
            float v0 = (tv.x - mm) * rr * g2.x + b2.x;
            float v1 = (tv.y - mm) * rr * g2.y + b2.y;
            float h0, l0, h1, l1;
            splitbf(v0, h0, l0); splitbf(v1, h1, l1);
            Yh[n * YPS + j] = packbf(h0, h1);
            Yl[n * YPS + j] = packbf(l0, l1);
        }
        __syncthreads();

        const float asc = attn_scale[l];
        const int colq = warp * 8 + lq;    // output column (0..191)

        for (int h = 0; h < NHD; h++) {
            // ===== qkv GEMM head h: 3-term split bf16 k16 =====
            {
                int sec = colq >> 6, d = colq & 63;
                const float* wq = qkv_w + ((size_t)(l * 3 + sec) * DD + h * HDIM + d) * DD;
                float acc[5][4];
#pragma unroll
                for (int mt = 0; mt < 5; mt++)
#pragma unroll
                    for (int i = 0; i < 4; i++) acc[mt][i] = 0.f;
                float2 pw0 = *(const float2*)(wq + 2 * l4);
                float2 pw1 = *(const float2*)(wq + 2 * l4 + 8);
                for (int ko = 0; ko < 12; ko++) {
                    float2 nw0 = make_float2(0.f, 0.f), nw1 = make_float2(0.f, 0.f);
                    if (ko < 11) {
                        nw0 = *(const float2*)(wq + (ko + 1) * 16 + 2 * l4);
                        nw1 = *(const float2*)(wq + (ko + 1) * 16 + 2 * l4 + 8);
                    }
                    float h0, lo0, h1, lo1, h2, lo2, h3, lo3;
                    splitbf(pw0.x, h0, lo0); splitbf(pw0.y, h1, lo1);
                    splitbf(pw1.x, h2, lo2); splitbf(pw1.y, h3, lo3);
                    unsigned bh0 = packbf(h0, h1), bh1 = packbf(h2, h3);
                    unsigned bl0 = packbf(lo0, lo1), bl1 = packbf(lo2, lo3);
                    int p0 = ko * 8 + l4;
#pragma unroll
                    for (int mt = 0; mt < 5; mt++) {
                        int r0 = mt * 16;
                        unsigned ah0 = Yh[(r0 + lq) * YPS + p0];
                        unsigned ah1 = Yh[(r0 + 8 + lq) * YPS + p0];
                        unsigned ah2 = Yh[(r0 + lq) * YPS + p0 + 4];
                        unsigned ah3 = Yh[(r0 + 8 + lq) * YPS + p0 + 4];
                        unsigned al0 = Yl[(r0 + lq) * YPS + p0];
                        unsigned al1 = Yl[(r0 + 8 + lq) * YPS + p0];
                        unsigned al2 = Yl[(r0 + lq) * YPS + p0 + 4];
                        unsigned al3 = Yl[(r0 + 8 + lq) * YPS + p0 + 4];
                        mma_bf16(acc[mt], ah0, ah1, ah2, ah3, bh0, bh1);
                        mma_bf16(acc[mt], ah0, ah1, ah2, ah3, bl0, bl1);
                        mma_bf16(acc[mt], al0, al1, al2, al3, bh0, bh1);
                    }
                    pw0 = nw0; pw1 = nw1;
                }
                int cc = warp * 8 + 2 * l4;
#pragma unroll
                for (int mt = 0; mt < 5; mt++) {
                    int rA = mt * 16 + lq, rB = rA + 8;
                    if (rA < 65) { S[rA * SSS + cc] = acc[mt][0]; S[rA * SSS + cc + 1] = acc[mt][1]; }
                    if (rB < 65) { S[rB * SSS + cc] = acc[mt][2]; S[rB * SSS + cc + 1] = acc[mt][3]; }
                }
            }
            __syncthreads();   // publish S

            // ===== banded attention (|i-j|<=3) -> packed bf16 Oh =====
            {
                float coef = 0.125f / temp[l * NHD + h];
                for (int i = warp; i < 65; i += NWARP) {
                    int jlo = (i - 3 < 0) ? 0 : i - 3;
                    int jhi = (i + 3 > 64) ? 64 : i + 3;
                    int cnt = jhi - jlo + 1;
                    float2 qv = *(const float2*)(S + i * SSS + 2 * lane);
                    float sc[7];
#pragma unroll
                    for (int jj = 0; jj < 7; jj++) {
                        if (jj < cnt) {
                            float2 kv = *(const float2*)(S + (jlo + jj) * SSS + 64 + 2 * lane);
                            float p = qv.x * kv.x + qv.y * kv.y;
#pragma unroll
                            for (int o = 16; o; o >>= 1) p += __shfl_xor_sync(0xffffffffu, p, o);
                            sc[jj] = p * coef;
                        }
                    }
                    float mx = sc[0];
#pragma unroll
                    for (int jj = 1; jj < 7; jj++) if (jj < cnt) mx = fmaxf(mx, sc[jj]);
                    float ssum = 0.f;
#pragma unroll
                    for (int jj = 0; jj < 7; jj++) if (jj < cnt) { sc[jj] = expf(sc[jj] - mx); ssum += sc[jj]; }
                    float inv = 1.0f / ssum;
                    float o0 = 0.f, o1 = 0.f;
#pragma unroll
                    for (int jj = 0; jj < 7; jj++) {
                        if (jj < cnt) {
                            float2 vv = *(const float2*)(S + (jlo + jj) * SSS + 128 + 2 * lane);
                            o0 += sc[jj] * vv.x;
                            o1 += sc[jj] * vv.y;
                        }
                    }
                    float h0, lo0, h1, lo1;
                    splitbf(o0 * inv, h0, lo0);
                    splitbf(o1 * inv, h1, lo1);
                    Ohh[i * OPS + lane] = packbf(h0, h1);
                    Ohl[i * OPS + lane] = packbf(lo0, lo1);
                }
            }
            __syncthreads();   // publish Oh

            // ===== proj partial (k=64): 3-term split bf16 k16 =====
            {
                const float* wp = proj_w + ((size_t)l * DD + colq) * DD + h * HDIM;
                float acc[5][4];
#pragma unroll
                for (int mt = 0; mt < 5; mt++)
#pragma unroll
                    for (int i = 0; i < 4; i++) acc[mt][i] = 0.f;
                float2 pw0 = *(const float2*)(wp + 2 * l4);
                float2 pw1 = *(const float2*)(wp + 2 * l4 + 8);
                for (int ko = 0; ko < 4; ko++) {
                    float2 nw0 = make_float2(0.f, 0.f), nw1 = make_float2(0.f, 0.f);
                    if (ko < 3) {
                        nw0 = *(const float2*)(wp + (ko + 1) * 16 + 2 * l4);
                        nw1 = *(const float2*)(wp + (ko + 1) * 16 + 2 * l4 + 8);
                    }
                    float h0, lo0, h1, lo1, h2, lo2, h3, lo3;
                    splitbf(pw0.x, h0, lo0); splitbf(pw0.y, h1, lo1);
                    splitbf(pw1.x, h2, lo2); splitbf(pw1.y, h3, lo3);
                    unsigned bh0 = packbf(h0, h1), bh1 = packbf(h2, h3);
                    unsigned bl0 = packbf(lo0, lo1), bl1 = packbf(lo2, lo3);
                    int p0 = ko * 8 + l4;
#pragma unroll
                    for (int mt = 0; mt < 5; mt++) {
                        int r0 = mt * 16;
                        unsigned ah0 = Ohh[(r0 + lq) * OPS + p0];
                        unsigned ah1 = Ohh[(r0 + 8 + lq) * OPS + p0];
                        unsigned ah2 = Ohh[(r0 + lq) * OPS + p0 + 4];
                        unsigned ah3 = Ohh[(r0 + 8 + lq) * OPS + p0 + 4];
                        unsigned al0 = Ohl[(r0 + lq) * OPS + p0];
                        unsigned al1 = Ohl[(r0 + 8 + lq) * OPS + p0];
                        unsigned al2 = Ohl[(r0 + lq) * OPS + p0 + 4];
                        unsigned al3 = Ohl[(r0 + 8 + lq) * OPS + p0 + 4];
                        mma_bf16(acc[mt], ah0, ah1, ah2, ah3, bh0, bh1);
                        mma_bf16(acc[mt], ah0, ah1, ah2, ah3, bl0, bl1);
                        mma_bf16(acc[mt], al0, al1, al2, al3, bh0, bh1);
                    }
                    pw0 = nw0; pw1 = nw1;
                }
                int cc = warp * 8 + 2 * l4;
                float pbias0 = (h == 0) ? proj_b[l * DD + cc] : 0.f;
                float pbias1 = (h == 0) ? proj_b[l * DD + cc + 1] : 0.f;
#pragma unroll
                for (int mt = 0; mt < 5; mt++) {
                    int rA = mt * 16 + lq, rB = rA + 8;
                    if (rA < 65) {
                        t[rA * DD + cc]     += asc * (acc[mt][0] + pbias0);
                        t[rA * DD + cc + 1] += asc * (acc[mt][1] + pbias1);
                    }
                    if (rB < 65) {
                        t[rB * DD + cc]     += asc * (acc[mt][2] + pbias0);
                        t[rB * DD + cc + 1] += asc * (acc[mt][3] + pbias1);
                    }
                }
            }
            __syncthreads();   // t updated; S/Oh reusable
        }

        // ---- LN2 -> Yf (fp32 for gating) ----
        ln_stats(t, 0, 65, sp->m, sp->rs);
        __syncthreads();
        for (int i = tid; i < 65 * DD; i += NTHR) {
            int n = i / DD, c = i % DD;
            Yf[n * YS + c] = (t[i] - sp->m[n]) * sp->rs[n] * n2_g[l * DD + c] + n2_b[l * DD + c];
        }
        for (int c = tid; c < DD; c += NTHR) Yf[65 * YS + c] = 0.f;
        __syncthreads();

        // ---- gating (fp32 Yf) ----
        for (int task = tid; task < NT * NE; task += NTHR) {
            int n = task >> 2, e = task & 3;
            const float* gw = gate_w + ((size_t)l * NE + e) * DD;
            float acc = gate_b[l * NE + e];
            for (int c = 0; c < DD; c += 4) {
                float4 y4 = *(const float4*)(Yf + n * YS + c);
                float4 w4 = *(const float4*)(gw + c);
                acc += dot4(y4, w4);
            }
            sp->gl[n * NE + e] = acc;
        }
        __syncthreads();
        // convert Yf in place to tf32; top-2 select in parallel
        for (int i = tid; i < 66 * DD; i += NTHR) {
            int n = i / DD, c = i % DD;
            ((unsigned*)Yf)[n * YS + c] = to_tf32(Yf[n * YS + c]);
        }
        if (tid < NT) {
            float vv[4] = { sp->gl[tid * 4 + 0], sp->gl[tid * 4 + 1],
                            sp->gl[tid * 4 + 2], sp->gl[tid * 4 + 3] };
            int i0 = 0; float bmax = vv[0];
#pragma unroll
            for (int e = 1; e < 4; e++) if (vv[e] > bmax) { bmax = vv[e]; i0 = e; }
            int i1 = -1; float b2v = -1e30f;
#pragma unroll
            for (int e = 0; e < 4; e++) if (e != i0 && vv[e] > b2v) { b2v = vv[e]; i1 = e; }
            float w1 = expf(b2v - bmax);
            float inv = 1.0f / (1.0f + w1);
            sp->seli[tid * 2 + 0] = i0;
            sp->seli[tid * 2 + 1] = i1;
            sp->selw[tid * 2 + 0] = inv;
            sp->selw[tid * 2 + 1] = w1 * inv;
        }
        __syncthreads();
        if (tid == 0) {
            float msc = mlp_scale[l];
            int cnt[4] = { 0, 0, 0, 0 };
            for (int n = 0; n < NT; n++) {
                for (int sidx = 0; sidx < 2; sidx++) {
                    int e = sp->seli[n * 2 + sidx];
                    sp->elist[e * 80 + cnt[e]] = n;
                    sp->ewt[e * 80 + cnt[e]] = sp->selw[n * 2 + sidx] * msc;
                    cnt[e]++;
                }
            }
            for (int e = 0; e < 4; e++) {
                while (cnt[e] % 16 != 0) {
                    sp->elist[e * 80 + cnt[e]] = 65;   // tf32 zero row
                    sp->ewt[e * 80 + cnt[e]] = 0.f;
                    cnt[e]++;
                }
                sp->ecnt[e] = cnt[e];
            }
        }
        __syncthreads();

        // ---- expert FFNs on tensor cores (single tf32, as R12) ----
        const unsigned* YT = (const unsigned*)Yf;
        unsigned* Htf = (unsigned*)S;
        for (int e = 0; e < NE; e++) {
            int cnt = sp->ecnt[e];
            if (cnt == 0) continue;
            const float* w1b = e_w1 + (size_t)(l * NE + e) * DH * DD;
            const float* w2b = e_w2 + (size_t)(l * NE + e) * DD * DH;
            const float* b1p = e_b1 + (size_t)(l * NE + e) * DH;
            const float* b2p = e_b2 + (size_t)(l * NE + e) * DD;
            int base0 = e * 80;
            for (int mb = 0; mb < cnt; mb += 48) {
                int nmt = (cnt - mb) >> 4; if (nmt > 3) nmt = 3;
                int tokA[3], tokB[3];
#pragma unroll
                for (int mt = 0; mt < 3; mt++) if (mt < nmt) {
                    tokA[mt] = sp->elist[base0 + mb + mt * 16 + lq];
                    tokB[mt] = sp->elist[base0 + mb + mt * 16 + 8 + lq];
                }
                float acc2[3][4];
#pragma unroll
                for (int mt = 0; mt < 3; mt++)
#pragma unroll
                    for (int i = 0; i < 4; i++) acc2[mt][i] = 0.f;

                for (int kh = 0; kh < 2; kh++) {
                    float acc1[3][4];
#pragma unroll
                    for (int mt = 0; mt < 3; mt++)
#pragma unroll
                        for (int i = 0; i < 4; i++) acc1[mt][i] = 0.f;
                    {
                        const float* wb = w1b + (size_t)(kh * 192 + warp * 8 + lq) * DD + l4;
                        float pb0 = wb[0], pb1 = wb[4];
#pragma unroll 2
                        for (int ks = 0; ks < 24; ks++) {
                            float nb0 = 0.f, nb1 = 0.f;
                            if (ks < 23) { nb0 = wb[(ks + 1) * 8]; nb1 = wb[(ks + 1) * 8 + 4]; }
                            unsigned ub0 = to_tf32(pb0), ub1 = to_tf32(pb1);
                            int k0 = ks * 8 + l4;
#pragma unroll
                            for (int mt = 0; mt < 3; mt++) if (mt < nmt) {
                                unsigned a0 = YT[tokA[mt] * YS + k0];
                                unsigned a1 = YT[tokB[mt] * YS + k0];
                                unsigned a2 = YT[tokA[mt] * YS + k0 + 4];
                                unsigned a3 = YT[tokB[mt] * YS + k0 + 4];
                                mma_tf32(acc1[mt], a0, a1, a2, a3, ub0, ub1);
                            }
                            pb0 = nb0; pb1 = nb1;
                        }
                    }
                    {
                        int cl = warp * 8 + 2 * l4;
                        float bia0 = b1p[kh * 192 + cl], bia1 = b1p[kh * 192 + cl + 1];
#pragma unroll
                        for (int mt = 0; mt < 3; mt++) if (mt < nmt) {
                            int rA = mt * 16 + lq, rB = rA + 8;
                            Htf[rA * HTS + cl]     = to_tf32(gelu_exact(acc1[mt][0] + bia0));
                            Htf[rA * HTS + cl + 1] = to_tf32(gelu_exact(acc1[mt][1] + bia1));
                            Htf[rB * HTS + cl]     = to_tf32(gelu_exact(acc1[mt][2] + bia0));
                            Htf[rB * HTS + cl + 1] = to_tf32(gelu_exact(acc1[mt][3] + bia1));
                        }
                    }
                    __syncthreads();
                    {
                        const float* wb = w2b + (size_t)(warp * 8 + lq) * DH + kh * 192 + l4;
                        float pb0 = wb[0], pb1 = wb[4];
#pragma unroll 2
                        for (int ks = 0; ks < 24; ks++) {
                            float nb0 = 0.f, nb1 = 0.f;
                            if (ks < 23) { nb0 = wb[(ks + 1) * 8]; nb1 = wb[(ks + 1) * 8 + 4]; }
                            unsigned ub0 = to_tf32(pb0), ub1 = to_tf32(pb1);
                            int k0 = ks * 8 + l4;
#pragma unroll
                            for (int mt = 0; mt < 3; mt++) if (mt < nmt) {
                                unsigned a0 = Htf[(mt * 16 + lq) * HTS + k0];
                                unsigned a1 = Htf[(mt * 16 + 8 + lq) * HTS + k0];
                                unsigned a2 = Htf[(mt * 16 + lq) * HTS + k0 + 4];
                                unsigned a3 = Htf[(mt * 16 + 8 + lq) * HTS + k0 + 4];
                                mma_tf32(acc2[mt], a0, a1, a2, a3, ub0, ub1);
                            }
                            pb0 = nb0; pb1 = nb1;
                        }
                    }
                    __syncthreads();
                }
                {
                    int c = warp * 8 + 2 * l4;
                    float bb0 = b2p[c], bb1 = b2p[c + 1];
#pragma unroll
                    for (int mt = 0; mt < 3; mt++) if (mt < nmt) {
                        int iA = base0 + mb + mt * 16 + lq, iB = iA + 8;
                        int tA = sp->elist[iA]; float wA = sp->ewt[iA];
                        int tB = sp->elist[iB]; float wB = sp->ewt[iB];
                        t[tA * DD + c]     += wA * (acc2[mt][0] + bb0);
                        t[tA * DD + c + 1] += wA * (acc2[mt][1] + bb1);
                        t[tB * DD + c]     += wB * (acc2[mt][2] + bb0);
                        t[tB * DD + c + 1] += wB * (acc2[mt][3] + bb1);
                    }
                }
                __syncthreads();
            }
        }
        __syncthreads();
    }

    // ======================= final norm + circulant head =======================
    ln_stats(t, 0, 1, sp->m, sp->rs);
    __syncthreads();
    float* cls = Yf;
    for (int c = tid; c < DD; c += NTHR)
        cls[c] = (t[c] - sp->m[0]) * sp->rs[0] * norm_g[c] + norm_b[c];
    __syncthreads();
    float* HH = S;
    for (int ko = tid; ko < 2 * DD; ko += NTHR) {
        int k = ko / 96, o = ko % 96;
        float acc = hc_b[ko];
#pragma unroll
        for (int j = 0; j < 4; j++) {
            const float* w = hc_w + ((size_t)((k - j) & 3) * 96 + o) * 48;
            const float* xv = cls + j * 48;
#pragma unroll
            for (int c = 0; c < 48; c += 4) {
                float4 w4 = *(const float4*)(w + c);
                float4 x4 = *(const float4*)(xv + c);
                acc += dot4(x4, w4);
            }
        }
        HH[ko] = gelu_exact(acc);
    }
    __syncthreads();
    for (int ci = tid; ci < NCLS; ci += NTHR) {
        const float* w = head_w + (size_t)ci * (2 * DD);
        float acc = head_b[ci];
        for (int c = 0; c < 2 * DD; c += 4) {
            float4 w4 = *(const float4*)(w + c);
            float4 h4 = *(const float4*)(HH + c);
            acc += dot4(h4, w4);
        }
        out[b * NCLS + ci] = acc;
    }
}

extern "C" void kernel_launch(void* const* d_in, const int* in_sizes, int n_in,
                              void* d_out, int out_size) {
    (void)in_sizes; (void)n_in; (void)out_size;
    const float* x          = (const float*)d_in[0];
    const float* conv_w     = (const float*)d_in[1];
    const float* conv_b     = (const float*)d_in[2];
    const float* pe_g       = (const float*)d_in[3];
    const float* pe_b       = (const float*)d_in[4];
    const float* cls_token  = (const float*)d_in[5];
    const float* pos_embed  = (const float*)d_in[6];
    const float* n1_g       = (const float*)d_in[7];
    const float* n1_b       = (const float*)d_in[8];
    const float* qkv_w      = (const float*)d_in[9];
    const float* temp       = (const float*)d_in[10];
    const float* proj_w     = (const float*)d_in[11];
    const float* proj_b     = (const float*)d_in[12];
    const float* n2_g       = (const float*)d_in[13];
    const float* n2_b       = (const float*)d_in[14];
    const float* gate_w     = (const float*)d_in[15];
    const float* gate_b     = (const float*)d_in[16];
    const float* e_w1       = (const float*)d_in[17];
    const float* e_b1       = (const float*)d_in[18];
    const float* e_w2       = (const float*)d_in[19];
    const float* e_b2       = (const float*)d_in[20];
    const float* attn_scale = (const float*)d_in[21];
    const float* mlp_scale  = (const float*)d_in[22];
    const float* norm_g     = (const float*)d_in[23];
    const float* norm_b     = (const float*)d_in[24];
    const float* hc_w       = (const float*)d_in[25];
    const float* hc_b       = (const float*)d_in[26];
    const float* head_w     = (const float*)d_in[27];
    const float* head_b     = (const float*)d_in[28];

    cudaFuncSetAttribute(hypervit_kernel, cudaFuncAttributeMaxDynamicSharedMemorySize,
                         (int)sizeof(SM));
    hypervit_kernel<<<NB, NTHR, sizeof(SM)>>>(
        x, conv_w, conv_b, pe_g, pe_b, cls_token, pos_embed,
        n1_g, n1_b, qkv_w, temp, proj_w, proj_b, n2_g, n2_b,
        gate_w, gate_b, e_w1, e_b1, e_w2, e_b2,
        attn_scale, mlp_scale, norm_g, norm_b, hc_w, hc_b,
        head_w, head_b, (float*)d_out);
}

// round 17
// speedup vs baseline: 1.5613x; 1.2539x over previous
#include <cuda_runtime.h>
#include <math.h>

#define NB 128
#define DD 192
#define DEPTHL 12
#define NHD 3
#define HDIM 64
#define NE 4
#define NT 65
#define NCLS 100
#define DH 384
#define NTHR 768
#define NWARP 24
#define YPS 100         // packed bf16 Y row stride (u32 words; 96 used)
#define OPS 36          // packed bf16 Oh row stride (32 used)
#define SSS 192         // S row stride (fp32)
#define HPS 196         // packed H row stride (u32; 192 used)
#define MB 32           // MoE m-block rows

// pre-packed weights (bf16 hi/lo, fragment-order swizzle)
__device__ unsigned QKVP[12 * 576 * 192];
__device__ unsigned PROJP[12 * 192 * 192];
__device__ unsigned W1P[12 * 4 * 384 * 192];
__device__ unsigned W2P[12 * 4 * 192 * 384];

struct __align__(16) SM {
    float t[66 * DD];
    float S[66 * SSS];           // qkv out fp32; MoE: Hh(32xHPS)+Hl(32xHPS) alias
    unsigned YU[16000];          // Yh [0,8000) + Yl [8000,16000), 80 x YPS
    unsigned OhU[2 * 80 * OPS];  // Ohh / Ohl packed
    float m[72], rs[72];
    float gl[NT * NE];
    float selw[NT * 2];
    float ewt[NE * 80];
    int   seli[NT * 2];
    int   elist[NE * 80];
    int   ecnt[NE];
};

__device__ __forceinline__ float gelu_exact(float x) {
    return 0.5f * x * (1.0f + erff(x * 0.70710678118654752f));
}
__device__ __forceinline__ float dot4(float4 a, float4 b) {
    return a.x * b.x + a.y * b.y + a.z * b.z + a.w * b.w;
}
__device__ __forceinline__ void splitbf(float f, float& hi, float& lo) {
    hi = __uint_as_float(__float_as_uint(f) & 0xffff0000u);
    lo = f - hi;
}
__device__ __forceinline__ unsigned packbf(float lo_v, float hi_v) {  // lo_v -> low half
    unsigned r;
    asm("cvt.rn.bf16x2.f32 %0, %1, %2;" : "=r"(r) : "f"(hi_v), "f"(lo_v));
    return r;
}
__device__ __forceinline__ void mma_bf16(float* c, unsigned a0, unsigned a1, unsigned a2, unsigned a3,
                                         unsigned b0, unsigned b1) {
    asm volatile(
        "mma.sync.aligned.m16n8k16.row.col.f32.bf16.bf16.f32 "
        "{%0,%1,%2,%3},{%4,%5,%6,%7},{%8,%9},{%0,%1,%2,%3};"
        : "+f"(c[0]), "+f"(c[1]), "+f"(c[2]), "+f"(c[3])
        : "r"(a0), "r"(a1), "r"(a2), "r"(a3), "r"(b0), "r"(b1));
}

// packs one k16 group: dst words [hi(l4), hi(l4+4), lo(l4), lo(l4+4)] x l4
__global__ void pack_weights(const float* __restrict__ src, unsigned* __restrict__ dst,
                             int nrows, int K) {
    int g = blockIdx.x * blockDim.x + threadIdx.x;
    int gpr = K >> 4;
    if (g >= nrows * gpr) return;
    int row = g / gpr, grp = g - row * gpr;
    const float* s = src + (size_t)row * K + grp * 16;
    unsigned* d = dst + (size_t)row * K + grp * 16;
    float v[16];
#pragma unroll
    for (int i = 0; i < 16; i++) v[i] = s[i];
#pragma unroll
    for (int l4 = 0; l4 < 4; l4++) {
        int w0 = l4, w1 = l4 + 4;
        float h00, l00, h01, l01, h10, l10, h11, l11;
        splitbf(v[2 * w0], h00, l00); splitbf(v[2 * w0 + 1], h01, l01);
        splitbf(v[2 * w1], h10, l10); splitbf(v[2 * w1 + 1], h11, l11);
        d[l4 * 4 + 0] = packbf(h00, h01);
        d[l4 * 4 + 1] = packbf(h10, h11);
        d[l4 * 4 + 2] = packbf(l00, l01);
        d[l4 * 4 + 3] = packbf(l10, l11);
    }
}

__device__ __forceinline__ void ln_stats(const float* __restrict__ base, int n0, int n1,
                                         float* __restrict__ m, float* __restrict__ rs) {
    int warp = threadIdx.x >> 5, lane = threadIdx.x & 31;
    for (int n = n0 + warp; n < n1; n += NWARP) {
        const float* row = base + n * DD;
        float s = 0.f;
        for (int c = lane; c < DD; c += 32) s += row[c];
#pragma unroll
        for (int o = 16; o; o >>= 1) s += __shfl_xor_sync(0xffffffffu, s, o);
        float mm = s * (1.0f / DD);
        float q = 0.f;
        for (int c = lane; c < DD; c += 32) { float d = row[c] - mm; q += d * d; }
#pragma unroll
        for (int o = 16; o; o >>= 1) q += __shfl_xor_sync(0xffffffffu, q, o);
        if (lane == 0) { m[n] = mm; rs[n] = rsqrtf(q * (1.0f / DD) + 1e-5f); }
    }
}

__global__ void __launch_bounds__(NTHR, 1) hypervit_kernel(
    const float* __restrict__ x, const float* __restrict__ conv_w, const float* __restrict__ conv_b,
    const float* __restrict__ pe_g, const float* __restrict__ pe_b,
    const float* __restrict__ cls_token, const float* __restrict__ pos_embed,
    const float* __restrict__ n1_g, const float* __restrict__ n1_b,
    const float* __restrict__ temp,
    const float* __restrict__ proj_b,
    const float* __restrict__ n2_g, const float* __restrict__ n2_b,
    const float* __restrict__ gate_w, const float* __restrict__ gate_b,
    const float* __restrict__ e_b1, const float* __restrict__ e_b2,
    const float* __restrict__ attn_scale, const float* __restrict__ mlp_scale,
    const float* __restrict__ norm_g, const float* __restrict__ norm_b,
    const float* __restrict__ hc_w, const float* __restrict__ hc_b,
    const float* __restrict__ head_w, const float* __restrict__ head_b,
    float* __restrict__ out)
{
    extern __shared__ char smraw[];
    SM* sp = (SM*)smraw;
    const int b = blockIdx.x;
    const int tid = threadIdx.x;
    const int warp = tid >> 5, lane = tid & 31;
    const int l4 = lane & 3, lq = lane >> 2;
    float* t = sp->t;
    float* S = sp->S;
    unsigned* Yh = sp->YU;
    unsigned* Yl = sp->YU + 8000;
    unsigned* Ohh = sp->OhU;
    unsigned* Ohl = sp->OhU + 80 * OPS;

    // zero garbage-sensitive pad rows once (qkv/proj m-tiles reach row 79)
    for (int i = tid; i < 15 * YPS; i += NTHR) { Yh[65 * YPS + i] = 0; Yl[65 * YPS + i] = 0; }
    for (int i = tid; i < 15 * OPS; i += NTHR) { Ohh[65 * OPS + i] = 0; Ohl[65 * OPS + i] = 0; }

    // ======================= patch embed =======================
    {
        float* P = S;
        for (int i = tid; i < 64 * 48; i += NTHR) {
            int patch = i / 48, f = i % 48;
            int c = f >> 4, pi = (f >> 2) & 3, pj = f & 3;
            int ph = patch >> 3, pw = patch & 7;
            P[i] = x[((b * 3 + c) * 32 + ph * 4 + pi) * 32 + pw * 4 + pj];
        }
        __syncthreads();
        for (int task = tid; task < 64 * DD; task += NTHR) {
            int p = task / DD, c = task % DD;
            const float* w = conv_w + c * 48;
            float acc = conv_b[c];
#pragma unroll
            for (int k = 0; k < 48; k += 4) {
                float4 w4 = *(const float4*)(w + k);
                float4 p4 = *(const float4*)(P + p * 48 + k);
                acc += dot4(p4, w4);
            }
            t[(p + 1) * DD + c] = acc;
        }
        __syncthreads();
        ln_stats(t, 1, 65, sp->m, sp->rs);
        __syncthreads();
        for (int i = tid; i < 64 * DD; i += NTHR) {
            int n = 1 + i / DD, c = i % DD;
            t[n * DD + c] = (t[n * DD + c] - sp->m[n]) * sp->rs[n] * pe_g[c] + pe_b[c]
                            + pos_embed[n * DD + c];
        }
        for (int c = tid; c < DD; c += NTHR) {
            t[c] = cls_token[c] + pos_embed[c];
            t[65 * DD + c] = 0.f;
        }
    }
    __syncthreads();

    // ======================= transformer layers =======================
    for (int l = 0; l < DEPTHL; l++) {
        // ---- LN1 -> packed bf16 hi/lo Y ----
        ln_stats(t, 0, 65, sp->m, sp->rs);
        __syncthreads();
        for (int i = tid; i < 65 * 96; i += NTHR) {
            int n = i / 96, j = i - n * 96;
            float2 tv = *(const float2*)(t + n * DD + 2 * j);
            float2 g2 = *(const float2*)(n1_g + l * DD + 2 * j);
            float2 b2 = *(const float2*)(n1_b + l * DD + 2 * j);
            float mm = sp->m[n], rr = sp->rs[n];
            float v0 = (tv.x - mm) * rr * g2.x + b2.x;
            float v1 = (tv.y - mm) * rr * g2.y + b2.y;
            float h0, lo0, h1, lo1;
            splitbf(v0, h0, lo0); splitbf(v1, h1, lo1);
            Yh[n * YPS + j] = packbf(h0, h1);
            Yl[n * YPS + j] = packbf(lo0, lo1);
        }
        __syncthreads();

        const float asc = attn_scale[l];
        const int colq = warp * 8 + lq;

        for (int h = 0; h < NHD; h++) {
            // ===== qkv GEMM head h: 3-term bf16 k16, pre-packed weights =====
            {
                int sec = colq >> 6, d = colq & 63;
                const unsigned* wq = QKVP + ((size_t)((l * 3 + sec) * DD + h * HDIM + d)) * DD;
                float acc[5][4];
#pragma unroll
                for (int mt = 0; mt < 5; mt++)
#pragma unroll
                    for (int i = 0; i < 4; i++) acc[mt][i] = 0.f;
                uint4 pw = *(const uint4*)(wq + l4 * 4);
                for (int ko = 0; ko < 12; ko++) {
                    uint4 nw = make_uint4(0, 0, 0, 0);
                    if (ko < 11) nw = *(const uint4*)(wq + (ko + 1) * 16 + l4 * 4);
                    int p0 = ko * 8 + l4;
#pragma unroll
                    for (int mt = 0; mt < 5; mt++) {
                        int r0 = mt * 16;
                        unsigned ah0 = Yh[(r0 + lq) * YPS + p0];
                        unsigned ah1 = Yh[(r0 + 8 + lq) * YPS + p0];
                        unsigned ah2 = Yh[(r0 + lq) * YPS + p0 + 4];
                        unsigned ah3 = Yh[(r0 + 8 + lq) * YPS + p0 + 4];
                        unsigned al0 = Yl[(r0 + lq) * YPS + p0];
                        unsigned al1 = Yl[(r0 + 8 + lq) * YPS + p0];
                        unsigned al2 = Yl[(r0 + lq) * YPS + p0 + 4];
                        unsigned al3 = Yl[(r0 + 8 + lq) * YPS + p0 + 4];
                        mma_bf16(acc[mt], ah0, ah1, ah2, ah3, pw.x, pw.y);
                        mma_bf16(acc[mt], ah0, ah1, ah2, ah3, pw.z, pw.w);
                        mma_bf16(acc[mt], al0, al1, al2, al3, pw.x, pw.y);
                    }
                    pw = nw;
                }
                int cc = warp * 8 + 2 * l4;
#pragma unroll
                for (int mt = 0; mt < 5; mt++) {
                    int rA = mt * 16 + lq, rB = rA + 8;
                    if (rA < 65) { S[rA * SSS + cc] = acc[mt][0]; S[rA * SSS + cc + 1] = acc[mt][1]; }
                    if (rB < 65) { S[rB * SSS + cc] = acc[mt][2]; S[rB * SSS + cc + 1] = acc[mt][3]; }
                }
            }
            __syncthreads();

            // ===== banded attention -> packed bf16 Oh =====
            {
                float coef = 0.125f / temp[l * NHD + h];
                for (int i = warp; i < 65; i += NWARP) {
                    int jlo = (i - 3 < 0) ? 0 : i - 3;
                    int jhi = (i + 3 > 64) ? 64 : i + 3;
                    int cnt = jhi - jlo + 1;
                    float2 qv = *(const float2*)(S + i * SSS + 2 * lane);
                    float sc[7];
#pragma unroll
                    for (int jj = 0; jj < 7; jj++) {
                        if (jj < cnt) {
                            float2 kv = *(const float2*)(S + (jlo + jj) * SSS + 64 + 2 * lane);
                            float p = qv.x * kv.x + qv.y * kv.y;
#pragma unroll
                            for (int o = 16; o; o >>= 1) p += __shfl_xor_sync(0xffffffffu, p, o);
                            sc[jj] = p * coef;
                        }
                    }
                    float mx = sc[0];
#pragma unroll
                    for (int jj = 1; jj < 7; jj++) if (jj < cnt) mx = fmaxf(mx, sc[jj]);
                    float ssum = 0.f;
#pragma unroll
                    for (int jj = 0; jj < 7; jj++) if (jj < cnt) { sc[jj] = expf(sc[jj] - mx); ssum += sc[jj]; }
                    float inv = 1.0f / ssum;
                    float o0 = 0.f, o1 = 0.f;
#pragma unroll
                    for (int jj = 0; jj < 7; jj++) {
                        if (jj < cnt) {
                            float2 vv = *(const float2*)(S + (jlo + jj) * SSS + 128 + 2 * lane);
                            o0 += sc[jj] * vv.x;
                            o1 += sc[jj] * vv.y;
                        }
                    }
                    float h0, lo0, h1, lo1;
                    splitbf(o0 * inv, h0, lo0);
                    splitbf(o1 * inv, h1, lo1);
                    Ohh[i * OPS + lane] = packbf(h0, h1);
                    Ohl[i * OPS + lane] = packbf(lo0, lo1);
                }
            }
            __syncthreads();

            // ===== proj partial (k=64): 3-term bf16 k16, pre-packed =====
            {
                const unsigned* wp = PROJP + ((size_t)(l * DD + colq)) * DD;
                float acc[5][4];
#pragma unroll
                for (int mt = 0; mt < 5; mt++)
#pragma unroll
                    for (int i = 0; i < 4; i++) acc[mt][i] = 0.f;
                uint4 pw = *(const uint4*)(wp + (h * 4) * 16 + l4 * 4);
                for (int ko = 0; ko < 4; ko++) {
                    uint4 nw = make_uint4(0, 0, 0, 0);
                    if (ko < 3) nw = *(const uint4*)(wp + (h * 4 + ko + 1) * 16 + l4 * 4);
                    int p0 = ko * 8 + l4;
#pragma unroll
                    for (int mt = 0; mt < 5; mt++) {
                        int r0 = mt * 16;
                        unsigned ah0 = Ohh[(r0 + lq) * OPS + p0];
                        unsigned ah1 = Ohh[(r0 + 8 + lq) * OPS + p0];
                        unsigned ah2 = Ohh[(r0 + lq) * OPS + p0 + 4];
                        unsigned ah3 = Ohh[(r0 + 8 + lq) * OPS + p0 + 4];
                        unsigned al0 = Ohl[(r0 + lq) * OPS + p0];
                        unsigned al1 = Ohl[(r0 + 8 + lq) * OPS + p0];
                        unsigned al2 = Ohl[(r0 + lq) * OPS + p0 + 4];
                        unsigned al3 = Ohl[(r0 + 8 + lq) * OPS + p0 + 4];
                        mma_bf16(acc[mt], ah0, ah1, ah2, ah3, pw.x, pw.y);
                        mma_bf16(acc[mt], ah0, ah1, ah2, ah3, pw.z, pw.w);
                        mma_bf16(acc[mt], al0, al1, al2, al3, pw.x, pw.y);
                    }
                    pw = nw;
                }
                int cc = warp * 8 + 2 * l4;
                float pbias0 = (h == 0) ? proj_b[l * DD + cc] : 0.f;
                float pbias1 = (h == 0) ? proj_b[l * DD + cc + 1] : 0.f;
#pragma unroll
                for (int mt = 0; mt < 5; mt++) {
                    int rA = mt * 16 + lq, rB = rA + 8;
                    if (rA < 65) {
                        t[rA * DD + cc]     += asc * (acc[mt][0] + pbias0);
                        t[rA * DD + cc + 1] += asc * (acc[mt][1] + pbias1);
                    }
                    if (rB < 65) {
                        t[rB * DD + cc]     += asc * (acc[mt][2] + pbias0);
                        t[rB * DD + cc + 1] += asc * (acc[mt][3] + pbias1);
                    }
                }
            }
            __syncthreads();
        }

        // ---- LN2 stats; gating fused from t (fp32); LN2 -> packed Yh/Yl ----
        ln_stats(t, 0, 65, sp->m, sp->rs);
        __syncthreads();
        for (int task = tid; task < NT * NE; task += NTHR) {
            int n = task >> 2, e = task & 3;
            const float* gw = gate_w + ((size_t)l * NE + e) * DD;
            float mm = sp->m[n], rr = sp->rs[n];
            float acc = gate_b[l * NE + e];
            for (int c = 0; c < DD; c += 4) {
                float4 tv = *(const float4*)(t + n * DD + c);
                float4 g4 = *(const float4*)(n2_g + l * DD + c);
                float4 b4 = *(const float4*)(n2_b + l * DD + c);
                float4 w4 = *(const float4*)(gw + c);
                acc += ((tv.x - mm) * rr * g4.x + b4.x) * w4.x;
                acc += ((tv.y - mm) * rr * g4.y + b4.y) * w4.y;
                acc += ((tv.z - mm) * rr * g4.z + b4.z) * w4.z;
                acc += ((tv.w - mm) * rr * g4.w + b4.w) * w4.w;
            }
            sp->gl[n * NE + e] = acc;
        }
        for (int i = tid; i < 65 * 96; i += NTHR) {
            int n = i / 96, j = i - n * 96;
            float2 tv = *(const float2*)(t + n * DD + 2 * j);
            float2 g2 = *(const float2*)(n2_g + l * DD + 2 * j);
            float2 b2 = *(const float2*)(n2_b + l * DD + 2 * j);
            float mm = sp->m[n], rr = sp->rs[n];
            float v0 = (tv.x - mm) * rr * g2.x + b2.x;
            float v1 = (tv.y - mm) * rr * g2.y + b2.y;
            float h0, lo0, h1, lo1;
            splitbf(v0, h0, lo0); splitbf(v1, h1, lo1);
            Yh[n * YPS + j] = packbf(h0, h1);
            Yl[n * YPS + j] = packbf(lo0, lo1);
        }
        for (int j = tid; j < 96; j += NTHR) { Yh[65 * YPS + j] = 0; Yl[65 * YPS + j] = 0; }
        __syncthreads();
        if (tid < NT) {
            float vv[4] = { sp->gl[tid * 4 + 0], sp->gl[tid * 4 + 1],
                            sp->gl[tid * 4 + 2], sp->gl[tid * 4 + 3] };
            int i0 = 0; float bmax = vv[0];
#pragma unroll
            for (int e = 1; e < 4; e++) if (vv[e] > bmax) { bmax = vv[e]; i0 = e; }
            int i1 = -1; float b2v = -1e30f;
#pragma unroll
            for (int e = 0; e < 4; e++) if (e != i0 && vv[e] > b2v) { b2v = vv[e]; i1 = e; }
            float w1 = expf(b2v - bmax);
            float inv = 1.0f / (1.0f + w1);
            sp->seli[tid * 2 + 0] = i0;
            sp->seli[tid * 2 + 1] = i1;
            sp->selw[tid * 2 + 0] = inv;
            sp->selw[tid * 2 + 1] = w1 * inv;
        }
        __syncthreads();
        if (tid == 0) {
            float msc = mlp_scale[l];
            int cnt[4] = { 0, 0, 0, 0 };
            for (int n = 0; n < NT; n++) {
                for (int sidx = 0; sidx < 2; sidx++) {
                    int e = sp->seli[n * 2 + sidx];
                    sp->elist[e * 80 + cnt[e]] = n;
                    sp->ewt[e * 80 + cnt[e]] = sp->selw[n * 2 + sidx] * msc;
                    cnt[e]++;
                }
            }
            for (int e = 0; e < 4; e++) {
                while (cnt[e] % 16 != 0) {
                    sp->elist[e * 80 + cnt[e]] = 65;   // zero row
                    sp->ewt[e * 80 + cnt[e]] = 0.f;
                    cnt[e]++;
                }
                sp->ecnt[e] = cnt[e];
            }
        }
        __syncthreads();

        // ---- expert FFNs: 3-term bf16, pre-packed weights, 32-row blocks ----
        unsigned* Hh = (unsigned*)S;
        unsigned* Hl = Hh + MB * HPS;
        for (int e = 0; e < NE; e++) {
            int cnt = sp->ecnt[e];
            if (cnt == 0) continue;
            const float* b1p = e_b1 + (size_t)(l * NE + e) * DH;
            const float* b2p = e_b2 + (size_t)(l * NE + e) * DD;
            int base0 = e * 80;
            for (int mb = 0; mb < cnt; mb += MB) {
                int nmt = (cnt - mb) >> 4; if (nmt > 2) nmt = 2;
                int tokA[2], tokB[2];
#pragma unroll
                for (int mt = 0; mt < 2; mt++) if (mt < nmt) {
                    tokA[mt] = sp->elist[base0 + mb + mt * 16 + lq];
                    tokB[mt] = sp->elist[base0 + mb + mt * 16 + 8 + lq];
                }
                float acc2[2][4];
#pragma unroll
                for (int mt = 0; mt < 2; mt++)
#pragma unroll
                    for (int i = 0; i < 4; i++) acc2[mt][i] = 0.f;

                for (int kh = 0; kh < 2; kh++) {
                    float acc1[2][4];
#pragma unroll
                    for (int mt = 0; mt < 2; mt++)
#pragma unroll
                        for (int i = 0; i < 4; i++) acc1[mt][i] = 0.f;
                    // G1: K=192 (12 groups)
                    {
                        const unsigned* wp = W1P + ((size_t)(l * NE + e) * DH + kh * 192 + warp * 8 + lq) * DD;
                        uint4 pw = *(const uint4*)(wp + l4 * 4);
#pragma unroll 2
                        for (int g = 0; g < 12; g++) {
                            uint4 nw = make_uint4(0, 0, 0, 0);
                            if (g < 11) nw = *(const uint4*)(wp + (g + 1) * 16 + l4 * 4);
                            int p0 = g * 8 + l4;
#pragma unroll
                            for (int mt = 0; mt < 2; mt++) if (mt < nmt) {
                                unsigned ah0 = Yh[tokA[mt] * YPS + p0];
                                unsigned ah1 = Yh[tokB[mt] * YPS + p0];
                                unsigned ah2 = Yh[tokA[mt] * YPS + p0 + 4];
                                unsigned ah3 = Yh[tokB[mt] * YPS + p0 + 4];
                                unsigned al0 = Yl[tokA[mt] * YPS + p0];
                                unsigned al1 = Yl[tokB[mt] * YPS + p0];
                                unsigned al2 = Yl[tokA[mt] * YPS + p0 + 4];
                                unsigned al3 = Yl[tokB[mt] * YPS + p0 + 4];
                                mma_bf16(acc1[mt], ah0, ah1, ah2, ah3, pw.x, pw.y);
                                mma_bf16(acc1[mt], ah0, ah1, ah2, ah3, pw.z, pw.w);
                                mma_bf16(acc1[mt], al0, al1, al2, al3, pw.x, pw.y);
                            }
                            pw = nw;
                        }
                    }
                    // G1 epilogue -> packed H
                    {
                        int cl = warp * 8 + 2 * l4;
                        int wb_ = kh * 96 + warp * 4 + l4;
                        float bia0 = b1p[kh * 192 + cl], bia1 = b1p[kh * 192 + cl + 1];
#pragma unroll
                        for (int mt = 0; mt < 2; mt++) if (mt < nmt) {
                            int rA = mt * 16 + lq, rB = rA + 8;
                            float gA0 = gelu_exact(acc1[mt][0] + bia0), gA1 = gelu_exact(acc1[mt][1] + bia1);
                            float gB0 = gelu_exact(acc1[mt][2] + bia0), gB1 = gelu_exact(acc1[mt][3] + bia1);
                            float h0, lo0, h1, lo1;
                            splitbf(gA0, h0, lo0); splitbf(gA1, h1, lo1);
                            Hh[rA * HPS + wb_] = packbf(h0, h1);
                            Hl[rA * HPS + wb_] = packbf(lo0, lo1);
                            splitbf(gB0, h0, lo0); splitbf(gB1, h1, lo1);
                            Hh[rB * HPS + wb_] = packbf(h0, h1);
                            Hl[rB * HPS + wb_] = packbf(lo0, lo1);
                        }
                    }
                    __syncthreads();
                }
                // G2: K=384 (24 groups) over packed H
                {
                    const unsigned* wp = W2P + ((size_t)(l * NE + e) * DD + warp * 8 + lq) * DH;
                    uint4 pw = *(const uint4*)(wp + l4 * 4);
#pragma unroll 2
                    for (int g = 0; g < 24; g++) {
                        uint4 nw = make_uint4(0, 0, 0, 0);
                        if (g < 23) nw = *(const uint4*)(wp + (g + 1) * 16 + l4 * 4);
                        int p0 = g * 8 + l4;
#pragma unroll
                        for (int mt = 0; mt < 2; mt++) if (mt < nmt) {
                            int rA = mt * 16 + lq, rB = rA + 8;
                            unsigned ah0 = Hh[rA * HPS + p0];
                            unsigned ah1 = Hh[rB * HPS + p0];
                            unsigned ah2 = Hh[rA * HPS + p0 + 4];
                            unsigned ah3 = Hh[rB * HPS + p0 + 4];
                            unsigned al0 = Hl[rA * HPS + p0];
                            unsigned al1 = Hl[rB * HPS + p0];
                            unsigned al2 = Hl[rA * HPS + p0 + 4];
                            unsigned al3 = Hl[rB * HPS + p0 + 4];
                            mma_bf16(acc2[mt], ah0, ah1, ah2, ah3, pw.x, pw.y);
                            mma_bf16(acc2[mt], ah0, ah1, ah2, ah3, pw.z, pw.w);
                            mma_bf16(acc2[mt], al0, al1, al2, al3, pw.x, pw.y);
                        }
                        pw = nw;
                    }
                }
                // G2 epilogue: scatter into t
                {
                    int c = warp * 8 + 2 * l4;
                    float bb0 = b2p[c], bb1 = b2p[c + 1];
#pragma unroll
                    for (int mt = 0; mt < 2; mt++) if (mt < nmt) {
                        int iA = base0 + mb + mt * 16 + lq, iB = iA + 8;
                        int tA = sp->elist[iA]; float wA = sp->ewt[iA];
                        int tB = sp->elist[iB]; float wB = sp->ewt[iB];
                        t[tA * DD + c]     += wA * (acc2[mt][0] + bb0);
                        t[tA * DD + c + 1] += wA * (acc2[mt][1] + bb1);
                        t[tB * DD + c]     += wB * (acc2[mt][2] + bb0);
                        t[tB * DD + c + 1] += wB * (acc2[mt][3] + bb1);
                    }
                }
                __syncthreads();
            }
        }
        __syncthreads();
    }

    // ======================= final norm + circulant head =======================
    ln_stats(t, 0, 1, sp->m, sp->rs);
    __syncthreads();
    float* cls = (float*)sp->OhU;
    for (int c = tid; c < DD; c += NTHR)
        cls[c] = (t[c] - sp->m[0]) * sp->rs[0] * norm_g[c] + norm_b[c];
    __syncthreads();
    float* HH = S;
    for (int ko = tid; ko < 2 * DD; ko += NTHR) {
        int k = ko / 96, o = ko % 96;
        float acc = hc_b[ko];
#pragma unroll
        for (int j = 0; j < 4; j++) {
            const float* w = hc_w + ((size_t)((k - j) & 3) * 96 + o) * 48;
            const float* xv = cls + j * 48;
#pragma unroll
            for (int c = 0; c < 48; c += 4) {
                float4 w4 = *(const float4*)(w + c);
                float4 x4 = *(const float4*)(xv + c);
                acc += dot4(x4, w4);
            }
        }
        HH[ko] = gelu_exact(acc);
    }
    __syncthreads();
    for (int ci = tid; ci < NCLS; ci += NTHR) {
        const float* w = head_w + (size_t)ci * (2 * DD);
        float acc = head_b[ci];
        for (int c = 0; c < 2 * DD; c += 4) {
            float4 w4 = *(const float4*)(w + c);
            float4 h4 = *(const float4*)(HH + c);
            acc += dot4(h4, w4);
        }
        out[b * NCLS + ci] = acc;
    }
}

static unsigned* dev_ptr(const void* sym) {
    void* p = nullptr;
    cudaGetSymbolAddress(&p, sym);
    return (unsigned*)p;
}

extern "C" void kernel_launch(void* const* d_in, const int* in_sizes, int n_in,
                              void* d_out, int out_size) {
    (void)in_sizes; (void)n_in; (void)out_size;
    const float* x          = (const float*)d_in[0];
    const float* conv_w     = (const float*)d_in[1];
    const float* conv_b     = (const float*)d_in[2];
    const float* pe_g       = (const float*)d_in[3];
    const float* pe_b       = (const float*)d_in[4];
    const float* cls_token  = (const float*)d_in[5];
    const float* pos_embed  = (const float*)d_in[6];
    const float* n1_g       = (const float*)d_in[7];
    const float* n1_b       = (const float*)d_in[8];
    const float* qkv_w      = (const float*)d_in[9];
    const float* temp       = (const float*)d_in[10];
    const float* proj_w     = (const float*)d_in[11];
    const float* proj_b     = (const float*)d_in[12];
    const float* n2_g       = (const float*)d_in[13];
    const float* n2_b       = (const float*)d_in[14];
    const float* gate_w     = (const float*)d_in[15];
    const float* gate_b     = (const float*)d_in[16];
    const float* e_w1       = (const float*)d_in[17];
    const float* e_b1       = (const float*)d_in[18];
    const float* e_w2       = (const float*)d_in[19];
    const float* e_b2       = (const float*)d_in[20];
    const float* attn_scale = (const float*)d_in[21];
    const float* mlp_scale  = (const float*)d_in[22];
    const float* norm_g     = (const float*)d_in[23];
    const float* norm_b     = (const float*)d_in[24];
    const float* hc_w       = (const float*)d_in[25];
    const float* hc_b       = (const float*)d_in[26];
    const float* head_w     = (const float*)d_in[27];
    const float* head_b     = (const float*)d_in[28];

    static unsigned* qkvp = nullptr;
    static unsigned* projp = nullptr;
    static unsigned* w1p = nullptr;
    static unsigned* w2p = nullptr;
    if (!qkvp) {
        qkvp  = dev_ptr(QKVP);
        projp = dev_ptr(PROJP);
        w1p   = dev_ptr(W1P);
        w2p   = dev_ptr(W2P);
        cudaFuncSetAttribute(hypervit_kernel, cudaFuncAttributeMaxDynamicSharedMemorySize,
                             (int)sizeof(SM));
    }

    {
        int n1 = 12 * 576 * 12;       // groups
        pack_weights<<<(n1 + 255) / 256, 256>>>(qkv_w, qkvp, 12 * 576, 192);
        int n2 = 12 * 192 * 12;
        pack_weights<<<(n2 + 255) / 256, 256>>>(proj_w, projp, 12 * 192, 192);
        int n3 = 12 * 4 * 384 * 12;
        pack_weights<<<(n3 + 255) / 256, 256>>>(e_w1, w1p, 12 * 4 * 384, 192);
        int n4 = 12 * 4 * 192 * 24;
        pack_weights<<<(n4 + 255) / 256, 256>>>(e_w2, w2p, 12 * 4 * 192, 384);
    }

    hypervit_kernel<<<NB, NTHR, sizeof(SM)>>>(
        x, conv_w, conv_b, pe_g, pe_b, cls_token, pos_embed,
        n1_g, n1_b, temp, proj_b, n2_g, n2_b,
        gate_w, gate_b, e_b1, e_b2,
        attn_scale, mlp_scale, norm_g, norm_b, hc_w, hc_b,
        head_w, head_b, (float*)d_out);
}